// round 1
// baseline (speedup 1.0000x reference)
#include <cuda_runtime.h>
#include <cuda_bf16.h>
#include <cstdio>

// ---------------- problem constants ----------------
#define BATCH   4
#define LSEQ    2048
#define NROWS   (BATCH*LSEQ)        // 8192
#define DIM     512
#define D_INNER 1024
#define D_STATE 16
#define D_CONV  4
#define DT_RANK 32
#define XDBL    (DT_RANK + 2*D_STATE)  // 64
#define D_GEOM  256
#define EPSV    1e-5f

// ---------------- scratch (device globals; no allocation) ----------------
__device__ float g_hln  [NROWS * DIM];        // layernorm(x)
__device__ float g_xz   [NROWS * 2 * D_INNER];// in_proj output (xm | z)
__device__ float g_xconv[NROWS * D_INNER];    // silu(conv(xm))
__device__ float g_xdbl [NROWS * XDBL];       // x_proj output (dt|B|C)
__device__ float g_delta[NROWS * D_INNER];    // softplus(dt@W+b)
__device__ float g_yscan[NROWS * D_INNER];    // scan output * silu(z)
__device__ float g_hout [NROWS * DIM];        // mixer output
__device__ float g_match[NROWS * DIM];        // pre-LN match
__device__ float g_geom [NROWS * D_GEOM];     // pre-LN geom

// ---------------- layernorm ----------------
__global__ void layernorm_kernel(const float* __restrict__ in,
                                 const float* __restrict__ w,
                                 const float* __restrict__ b,
                                 float* __restrict__ out, int cols)
{
    int row = blockIdx.x;
    const float* p = in + (size_t)row * cols;
    float s = 0.f, sq = 0.f;
    for (int c = threadIdx.x; c < cols; c += blockDim.x) {
        float v = p[c]; s += v; sq += v * v;
    }
    int lane = threadIdx.x & 31, wid = threadIdx.x >> 5;
    #pragma unroll
    for (int o = 16; o; o >>= 1) {
        s  += __shfl_xor_sync(0xffffffffu, s,  o);
        sq += __shfl_xor_sync(0xffffffffu, sq, o);
    }
    __shared__ float shs[8], shq[8];
    if (!lane) { shs[wid] = s; shq[wid] = sq; }
    __syncthreads();
    if (threadIdx.x == 0) {
        float ts = 0.f, tq = 0.f;
        int nw = (blockDim.x + 31) >> 5;
        for (int i = 0; i < nw; i++) { ts += shs[i]; tq += shq[i]; }
        float mu  = ts / cols;
        float var = tq / cols - mu * mu;
        shs[0] = mu;
        shq[0] = rsqrtf(var + EPSV);
    }
    __syncthreads();
    float mu = shs[0], inv = shq[0];
    float* o = out + (size_t)row * cols;
    for (int c = threadIdx.x; c < cols; c += blockDim.x)
        o[c] = (p[c] - mu) * inv * w[c] + b[c];
}

// ---------------- generic tiled SGEMM: C[M,N] = A[M,K(lda)] * B[N,K]^T ----------------
// EPI: 0 none, 1 softplus(acc+bias), 2 acc+bias+resid, 3 acc+bias
#define EPI_NONE     0
#define EPI_SOFTPL   1
#define EPI_RESID    2
#define EPI_BIAS     3

template<int EPI>
__global__ __launch_bounds__(256)
void sgemm_kernel(const float* __restrict__ A, int lda,
                  const float* __restrict__ B,
                  const float* __restrict__ bias,
                  const float* __restrict__ resid,
                  float* __restrict__ C,
                  int M, int N, int K)
{
    const int BM = 64, BN = 64, BK = 16;
    __shared__ float As[BK][BM];
    __shared__ float Bs[BK][BN];

    int bm = blockIdx.y * BM;
    int bn = blockIdx.x * BN;
    int tid = threadIdx.x;
    int tx = tid & 15;        // N direction (4 cols each)
    int ty = tid >> 4;        // M direction (4 rows each)

    int lr = tid >> 2;            // 0..63 load row
    int lc = (tid & 3) << 2;      // 0,4,8,12 load col (k)

    float acc[4][4] = {};

    for (int k0 = 0; k0 < K; k0 += BK) {
        float4 a4 = *reinterpret_cast<const float4*>(&A[(size_t)(bm + lr) * lda + k0 + lc]);
        float4 b4 = *reinterpret_cast<const float4*>(&B[(size_t)(bn + lr) * K   + k0 + lc]);
        As[lc + 0][lr] = a4.x; As[lc + 1][lr] = a4.y;
        As[lc + 2][lr] = a4.z; As[lc + 3][lr] = a4.w;
        Bs[lc + 0][lr] = b4.x; Bs[lc + 1][lr] = b4.y;
        Bs[lc + 2][lr] = b4.z; Bs[lc + 3][lr] = b4.w;
        __syncthreads();
        #pragma unroll
        for (int k = 0; k < BK; k++) {
            float4 av = *reinterpret_cast<const float4*>(&As[k][ty << 2]);
            float4 bv = *reinterpret_cast<const float4*>(&Bs[k][tx << 2]);
            float am[4] = {av.x, av.y, av.z, av.w};
            float bb[4] = {bv.x, bv.y, bv.z, bv.w};
            #pragma unroll
            for (int i = 0; i < 4; i++)
                #pragma unroll
                for (int j = 0; j < 4; j++)
                    acc[i][j] = fmaf(am[i], bb[j], acc[i][j]);
        }
        __syncthreads();
    }

    #pragma unroll
    for (int i = 0; i < 4; i++) {
        int row = bm + (ty << 2) + i;
        #pragma unroll
        for (int j = 0; j < 4; j++) {
            int col = bn + (tx << 2) + j;
            float v = acc[i][j];
            if (EPI == EPI_SOFTPL) {
                v += bias[col];
                v = (v > 20.f) ? v : log1pf(__expf(v));
            } else if (EPI == EPI_RESID) {
                v += bias[col] + resid[(size_t)row * N + col];
            } else if (EPI == EPI_BIAS) {
                v += bias[col];
            }
            C[(size_t)row * N + col] = v;
        }
    }
}

// ---------------- depthwise causal conv + silu ----------------
__global__ void conv_silu_kernel(const float* __restrict__ conv_w,
                                 const float* __restrict__ conv_b)
{
    int idx = blockIdx.x * blockDim.x + threadIdx.x;  // over NROWS*D_INNER
    if (idx >= NROWS * D_INNER) return;
    int d   = idx & (D_INNER - 1);
    int row = idx >> 10;
    int b   = row >> 11;        // /2048
    int t   = row & (LSEQ - 1);

    float w0 = conv_w[d * 4 + 0], w1 = conv_w[d * 4 + 1];
    float w2 = conv_w[d * 4 + 2], w3 = conv_w[d * 4 + 3];
    const float* base = g_xz + ((size_t)(b * LSEQ) ) * (2 * D_INNER) + d;
    float acc = conv_b[d];
    if (t >= 3) acc = fmaf(base[(size_t)(t - 3) * 2048], w0, acc);
    if (t >= 2) acc = fmaf(base[(size_t)(t - 2) * 2048], w1, acc);
    if (t >= 1) acc = fmaf(base[(size_t)(t - 1) * 2048], w2, acc);
    acc = fmaf(base[(size_t)t * 2048], w3, acc);
    // silu
    float s = acc / (1.f + __expf(-acc));
    g_xconv[(size_t)row * D_INNER + d] = s;
}

// ---------------- selective scan (fused +u*D and *silu(z)) ----------------
// block = 256 threads = 16 channels * 16 states; grid = B * D_INNER/16 = 256
__global__ __launch_bounds__(256)
void scan_kernel(const float* __restrict__ A_log,
                 const float* __restrict__ Dv)
{
    int b  = blockIdx.x >> 6;               // /64
    int d0 = (blockIdx.x & 63) << 4;        // *16
    int n  = threadIdx.x & 15;
    int ch = threadIdx.x >> 4;
    int d  = d0 + ch;

    float Av = -__expf(A_log[d * D_STATE + n]);
    float Dd = Dv[d];

    const float* deltaP = g_delta + (size_t)(b * LSEQ) * D_INNER + d;
    const float* uP     = g_xconv + (size_t)(b * LSEQ) * D_INNER + d;
    const float* xdP    = g_xdbl  + (size_t)(b * LSEQ) * XDBL;
    const float* zP     = g_xz    + (size_t)(b * LSEQ) * (2 * D_INNER) + D_INNER + d;
    float*       yP     = g_yscan + (size_t)(b * LSEQ) * D_INNER + d;

    float h = 0.f;
    #pragma unroll 4
    for (int t = 0; t < LSEQ; t++) {
        float dlt = deltaP[(size_t)t * D_INNER];
        float uu  = uP[(size_t)t * D_INNER];
        float Bv  = xdP[(size_t)t * XDBL + DT_RANK + n];
        float Cv  = xdP[(size_t)t * XDBL + DT_RANK + D_STATE + n];
        float dA  = __expf(dlt * Av);
        h = fmaf(dA, h, dlt * uu * Bv);
        float p = h * Cv;
        #pragma unroll
        for (int o = 8; o; o >>= 1)
            p += __shfl_xor_sync(0xffffffffu, p, o);
        if (n == 0) {
            float z = zP[(size_t)t * (2 * D_INNER)];
            float sig = z / (1.f + __expf(-z));
            yP[(size_t)t * D_INNER] = (p + uu * Dd) * sig;
        }
    }
}

// ---------------- launch ----------------
static float* sym(const void* symbol) {
    void* p = nullptr;
    cudaGetSymbolAddress(&p, symbol);
    return (float*)p;
}

extern "C" void kernel_launch(void* const* d_in, const int* in_sizes, int n_in,
                              void* d_out, int out_size)
{
    const float* x         = (const float*)d_in[0];
    const float* norm_w    = (const float*)d_in[1];
    const float* norm_b    = (const float*)d_in[2];
    const float* in_proj_w = (const float*)d_in[3];
    const float* conv_w    = (const float*)d_in[4];
    const float* conv_b    = (const float*)d_in[5];
    const float* x_proj_w  = (const float*)d_in[6];
    const float* dt_proj_w = (const float*)d_in[7];
    const float* dt_proj_b = (const float*)d_in[8];
    const float* A_log     = (const float*)d_in[9];
    const float* Dv        = (const float*)d_in[10];
    const float* mix_out_w = (const float*)d_in[11];
    const float* match_w   = (const float*)d_in[12];
    const float* match_b   = (const float*)d_in[13];
    const float* geom_w    = (const float*)d_in[14];
    const float* geom_b    = (const float*)d_in[15];
    const float* normm_w   = (const float*)d_in[16];
    const float* normm_b   = (const float*)d_in[17];
    const float* normg_w   = (const float*)d_in[18];
    const float* normg_b   = (const float*)d_in[19];

    float* p_hln   = sym(g_hln);
    float* p_xz    = sym(g_xz);
    float* p_xconv = sym(g_xconv);
    float* p_xdbl  = sym(g_xdbl);
    float* p_delta = sym(g_delta);
    float* p_yscan = sym(g_yscan);
    float* p_hout  = sym(g_hout);
    float* p_match = sym(g_match);
    float* p_geom  = sym(g_geom);

    float* out_match = (float*)d_out;                       // 8192*512
    float* out_geom  = (float*)d_out + (size_t)NROWS * DIM; // 8192*256

    // 1. h = layernorm(x)
    layernorm_kernel<<<NROWS, 256>>>(x, norm_w, norm_b, p_hln, DIM);

    // 2. xz = h @ in_proj_w^T   [8192, 2048]
    {
        dim3 grid(2 * D_INNER / 64, NROWS / 64);
        sgemm_kernel<EPI_NONE><<<grid, 256>>>(p_hln, DIM, in_proj_w,
                                              nullptr, nullptr, p_xz,
                                              NROWS, 2 * D_INNER, DIM);
    }

    // 3. xconv = silu(depthwise_conv(xm))
    conv_silu_kernel<<<(NROWS * D_INNER) / 256, 256>>>(conv_w, conv_b);

    // 4. x_dbl = xconv @ x_proj_w^T   [8192, 64]
    {
        dim3 grid(XDBL / 64, NROWS / 64);
        sgemm_kernel<EPI_NONE><<<grid, 256>>>(p_xconv, D_INNER, x_proj_w,
                                              nullptr, nullptr, p_xdbl,
                                              NROWS, XDBL, D_INNER);
    }

    // 5. delta = softplus(dt @ dt_proj_w^T + dt_proj_b)   [8192, 1024]
    {
        dim3 grid(D_INNER / 64, NROWS / 64);
        sgemm_kernel<EPI_SOFTPL><<<grid, 256>>>(p_xdbl, XDBL, dt_proj_w,
                                                dt_proj_b, nullptr, p_delta,
                                                NROWS, D_INNER, DT_RANK);
    }

    // 6. selective scan (fused + u*D, * silu(z))
    scan_kernel<<<BATCH * (D_INNER / 16), 256>>>(A_log, Dv);

    // 7. h_out = y @ mix_out_w^T   [8192, 512]
    {
        dim3 grid(DIM / 64, NROWS / 64);
        sgemm_kernel<EPI_NONE><<<grid, 256>>>(p_yscan, D_INNER, mix_out_w,
                                              nullptr, nullptr, p_hout,
                                              NROWS, DIM, D_INNER);
    }

    // 8. match_pre = residual + h_out @ match_w^T + match_b
    {
        dim3 grid(DIM / 64, NROWS / 64);
        sgemm_kernel<EPI_RESID><<<grid, 256>>>(p_hout, DIM, match_w,
                                               match_b, x, p_match,
                                               NROWS, DIM, DIM);
    }

    // 9. geom_pre = h_out @ geom_w^T + geom_b
    {
        dim3 grid(D_GEOM / 64, NROWS / 64);
        sgemm_kernel<EPI_BIAS><<<grid, 256>>>(p_hout, DIM, geom_w,
                                              geom_b, nullptr, p_geom,
                                              NROWS, D_GEOM, DIM);
    }

    // 10/11. final layernorms into d_out
    layernorm_kernel<<<NROWS, 256>>>(p_match, normm_w, normm_b, out_match, DIM);
    layernorm_kernel<<<NROWS, 256>>>(p_geom,  normg_w, normg_b, out_geom,  D_GEOM);
}

// round 2
// speedup vs baseline: 1.1012x; 1.1012x over previous
#include <cuda_runtime.h>
#include <cuda_bf16.h>

// ---------------- problem constants ----------------
#define BATCH   4
#define LSEQ    2048
#define NROWS   (BATCH*LSEQ)        // 8192
#define DIM     512
#define D_INNER 1024
#define D_STATE 16
#define D_CONV  4
#define DT_RANK 32
#define XDBL    (DT_RANK + 2*D_STATE)  // 64
#define D_GEOM  256
#define EPSV    1e-5f

// ---------------- scratch (device globals; no allocation) ----------------
__device__ float g_hln  [NROWS * DIM];
__device__ float g_xz   [NROWS * 2 * D_INNER];
__device__ float g_xconv[NROWS * D_INNER];
__device__ float g_xdbl [NROWS * XDBL];
__device__ float g_delta[NROWS * D_INNER];
__device__ float g_yscan[NROWS * D_INNER];
__device__ float g_hout [NROWS * DIM];
__device__ float g_match[NROWS * DIM];
__device__ float g_geom [NROWS * D_GEOM];

// ---------------- layernorm ----------------
__global__ void layernorm_kernel(const float* __restrict__ in,
                                 const float* __restrict__ w,
                                 const float* __restrict__ b,
                                 float* __restrict__ out, int cols)
{
    int row = blockIdx.x;
    const float* p = in + (size_t)row * cols;
    float s = 0.f, sq = 0.f;
    for (int c = threadIdx.x; c < cols; c += blockDim.x) {
        float v = p[c]; s += v; sq += v * v;
    }
    int lane = threadIdx.x & 31, wid = threadIdx.x >> 5;
    #pragma unroll
    for (int o = 16; o; o >>= 1) {
        s  += __shfl_xor_sync(0xffffffffu, s,  o);
        sq += __shfl_xor_sync(0xffffffffu, sq, o);
    }
    __shared__ float shs[8], shq[8];
    if (!lane) { shs[wid] = s; shq[wid] = sq; }
    __syncthreads();
    if (threadIdx.x == 0) {
        float ts = 0.f, tq = 0.f;
        int nw = (blockDim.x + 31) >> 5;
        for (int i = 0; i < nw; i++) { ts += shs[i]; tq += shq[i]; }
        float mu  = ts / cols;
        float var = tq / cols - mu * mu;
        shs[0] = mu;
        shq[0] = rsqrtf(var + EPSV);
    }
    __syncthreads();
    float mu = shs[0], inv = shq[0];
    float* o = out + (size_t)row * cols;
    for (int c = threadIdx.x; c < cols; c += blockDim.x)
        o[c] = (p[c] - mu) * inv * w[c] + b[c];
}

// ---------------- high-throughput SGEMM: C[M,N] = A[M,K(lda)] * B[N,K]^T -------
// 128xBN tile, BK=8, 8xTN per thread, register-prefetch pipeline.
// EPI: 0 none, 1 softplus(acc+bias), 2 acc+bias+resid, 3 acc+bias
#define EPI_NONE     0
#define EPI_SOFTPL   1
#define EPI_RESID    2
#define EPI_BIAS     3

template<int BN, int TN, int EPI>
__global__ __launch_bounds__(256, 2)
void sgemm_kernel(const float* __restrict__ A, int lda,
                  const float* __restrict__ B,
                  const float* __restrict__ bias,
                  const float* __restrict__ resid,
                  float* __restrict__ C,
                  int M, int N, int K)
{
    const int BM = 128, BK = 8, TM = 8;
    __shared__ float As[BK][BM];
    __shared__ float Bs[BK][BN];

    const int bm  = blockIdx.y * BM;
    const int bn  = blockIdx.x * BN;
    const int tid = threadIdx.x;
    const int tx  = tid & 15;     // 16 col groups
    const int ty  = tid >> 4;     // 16 row groups

    // ---- loader indices ----
    // A tile: BM(128) x BK(8) = 256 float4 -> 1 per thread
    const int arow = tid >> 1;            // 0..127
    const int akc  = (tid & 1) << 2;      // 0 or 4
    // B tile: BN x BK = BN*2 float4 (256 for BN=128, 128 for BN=64)
    const int brow = (BN == 128) ? (tid >> 1) : (tid >> 1);
    const int bkc  = (tid & 1) << 2;
    const bool bAct = (BN == 128) ? true : (tid < 128);

    const float* Aptr = A + (size_t)(bm + arow) * lda + akc;
    const float* Bptr = B + (size_t)(bn + brow) * K   + bkc;

    float4 aFetch = *reinterpret_cast<const float4*>(Aptr);
    float4 bFetch = bAct ? *reinterpret_cast<const float4*>(Bptr)
                         : make_float4(0.f, 0.f, 0.f, 0.f);

    float acc[TM][TN] = {};

    const int rA0 = ty << 2;          // rows rA0..+3
    const int rA1 = 64 + (ty << 2);   // rows rA1..+3
    const int cB0 = tx << 2;
    const int cB1 = (BN >> 1) + (tx << 2);   // only used when TN==8

    for (int k0 = 0; k0 < K; k0 += BK) {
        // store fetched tile to smem (transposed by k)
        As[akc + 0][arow] = aFetch.x;
        As[akc + 1][arow] = aFetch.y;
        As[akc + 2][arow] = aFetch.z;
        As[akc + 3][arow] = aFetch.w;
        if (bAct) {
            Bs[bkc + 0][brow] = bFetch.x;
            Bs[bkc + 1][brow] = bFetch.y;
            Bs[bkc + 2][brow] = bFetch.z;
            Bs[bkc + 3][brow] = bFetch.w;
        }
        __syncthreads();

        // prefetch next tile into registers
        if (k0 + BK < K) {
            aFetch = *reinterpret_cast<const float4*>(Aptr + k0 + BK);
            if (bAct)
                bFetch = *reinterpret_cast<const float4*>(Bptr + k0 + BK);
        }

        #pragma unroll
        for (int k = 0; k < BK; k++) {
            float4 a0 = *reinterpret_cast<const float4*>(&As[k][rA0]);
            float4 a1 = *reinterpret_cast<const float4*>(&As[k][rA1]);
            float4 b0 = *reinterpret_cast<const float4*>(&Bs[k][cB0]);
            float am[TM] = {a0.x, a0.y, a0.z, a0.w, a1.x, a1.y, a1.z, a1.w};
            float bb[TN];
            bb[0] = b0.x; bb[1] = b0.y; bb[2] = b0.z; bb[3] = b0.w;
            if (TN == 8) {
                float4 b1 = *reinterpret_cast<const float4*>(&Bs[k][cB1]);
                bb[4] = b1.x; bb[5] = b1.y; bb[6] = b1.z; bb[7] = b1.w;
            }
            #pragma unroll
            for (int i = 0; i < TM; i++)
                #pragma unroll
                for (int j = 0; j < TN; j++)
                    acc[i][j] = fmaf(am[i], bb[j], acc[i][j]);
        }
        __syncthreads();
    }

    // ---- epilogue ----
    #pragma unroll
    for (int i = 0; i < TM; i++) {
        int row = bm + ((i < 4) ? (rA0 + i) : (rA1 + i - 4));
        float* crow = C + (size_t)row * N;
        const float* rrow = (EPI == EPI_RESID) ? (resid + (size_t)row * N) : nullptr;
        #pragma unroll
        for (int jg = 0; jg < TN / 4; jg++) {
            int col = bn + ((jg == 0) ? cB0 : cB1);
            #pragma unroll
            for (int j = 0; j < 4; j++) {
                float v = acc[i][jg * 4 + j];
                int c = col + j;
                if (EPI == EPI_SOFTPL) {
                    v += bias[c];
                    v = (v > 20.f) ? v : log1pf(__expf(v));
                } else if (EPI == EPI_RESID) {
                    v += bias[c] + rrow[c];
                } else if (EPI == EPI_BIAS) {
                    v += bias[c];
                }
                crow[c] = v;
            }
        }
    }
}

// ---------------- depthwise causal conv + silu ----------------
__global__ void conv_silu_kernel(const float* __restrict__ conv_w,
                                 const float* __restrict__ conv_b)
{
    int idx = blockIdx.x * blockDim.x + threadIdx.x;
    if (idx >= NROWS * D_INNER) return;
    int d   = idx & (D_INNER - 1);
    int row = idx >> 10;
    int b   = row >> 11;
    int t   = row & (LSEQ - 1);

    float w0 = conv_w[d * 4 + 0], w1 = conv_w[d * 4 + 1];
    float w2 = conv_w[d * 4 + 2], w3 = conv_w[d * 4 + 3];
    const float* base = g_xz + (size_t)(b * LSEQ) * (2 * D_INNER) + d;
    float acc = conv_b[d];
    if (t >= 3) acc = fmaf(base[(size_t)(t - 3) * 2048], w0, acc);
    if (t >= 2) acc = fmaf(base[(size_t)(t - 2) * 2048], w1, acc);
    if (t >= 1) acc = fmaf(base[(size_t)(t - 1) * 2048], w2, acc);
    acc = fmaf(base[(size_t)t * 2048], w3, acc);
    float s = acc / (1.f + __expf(-acc));
    g_xconv[(size_t)row * D_INNER + d] = s;
}

// ---------------- selective scan (fused +u*D and *silu(z)) ----------------
__global__ __launch_bounds__(256)
void scan_kernel(const float* __restrict__ A_log,
                 const float* __restrict__ Dv)
{
    int b  = blockIdx.x >> 6;
    int d0 = (blockIdx.x & 63) << 4;
    int n  = threadIdx.x & 15;
    int ch = threadIdx.x >> 4;
    int d  = d0 + ch;

    float Av = -__expf(A_log[d * D_STATE + n]);
    float Dd = Dv[d];

    const float* deltaP = g_delta + (size_t)(b * LSEQ) * D_INNER + d;
    const float* uP     = g_xconv + (size_t)(b * LSEQ) * D_INNER + d;
    const float* xdP    = g_xdbl  + (size_t)(b * LSEQ) * XDBL;
    const float* zP     = g_xz    + (size_t)(b * LSEQ) * (2 * D_INNER) + D_INNER + d;
    float*       yP     = g_yscan + (size_t)(b * LSEQ) * D_INNER + d;

    float h = 0.f;
    #pragma unroll 4
    for (int t = 0; t < LSEQ; t++) {
        float dlt = deltaP[(size_t)t * D_INNER];
        float uu  = uP[(size_t)t * D_INNER];
        float Bv  = xdP[(size_t)t * XDBL + DT_RANK + n];
        float Cv  = xdP[(size_t)t * XDBL + DT_RANK + D_STATE + n];
        float dA  = __expf(dlt * Av);
        h = fmaf(dA, h, dlt * uu * Bv);
        float p = h * Cv;
        #pragma unroll
        for (int o = 8; o; o >>= 1)
            p += __shfl_xor_sync(0xffffffffu, p, o);
        if (n == 0) {
            float z = zP[(size_t)t * (2 * D_INNER)];
            float sig = z / (1.f + __expf(-z));
            yP[(size_t)t * D_INNER] = (p + uu * Dd) * sig;
        }
    }
}

// ---------------- launch ----------------
static float* sym(const void* symbol) {
    void* p = nullptr;
    cudaGetSymbolAddress(&p, symbol);
    return (float*)p;
}

extern "C" void kernel_launch(void* const* d_in, const int* in_sizes, int n_in,
                              void* d_out, int out_size)
{
    const float* x         = (const float*)d_in[0];
    const float* norm_w    = (const float*)d_in[1];
    const float* norm_b    = (const float*)d_in[2];
    const float* in_proj_w = (const float*)d_in[3];
    const float* conv_w    = (const float*)d_in[4];
    const float* conv_b    = (const float*)d_in[5];
    const float* x_proj_w  = (const float*)d_in[6];
    const float* dt_proj_w = (const float*)d_in[7];
    const float* dt_proj_b = (const float*)d_in[8];
    const float* A_log     = (const float*)d_in[9];
    const float* Dv        = (const float*)d_in[10];
    const float* mix_out_w = (const float*)d_in[11];
    const float* match_w   = (const float*)d_in[12];
    const float* match_b   = (const float*)d_in[13];
    const float* geom_w    = (const float*)d_in[14];
    const float* geom_b    = (const float*)d_in[15];
    const float* normm_w   = (const float*)d_in[16];
    const float* normm_b   = (const float*)d_in[17];
    const float* normg_w   = (const float*)d_in[18];
    const float* normg_b   = (const float*)d_in[19];

    float* p_hln   = sym(g_hln);
    float* p_xz    = sym(g_xz);
    float* p_xconv = sym(g_xconv);
    float* p_xdbl  = sym(g_xdbl);
    float* p_delta = sym(g_delta);
    float* p_yscan = sym(g_yscan);
    float* p_hout  = sym(g_hout);
    float* p_match = sym(g_match);
    float* p_geom  = sym(g_geom);

    float* out_match = (float*)d_out;
    float* out_geom  = (float*)d_out + (size_t)NROWS * DIM;

    // 1. h = layernorm(x)
    layernorm_kernel<<<NROWS, 256>>>(x, norm_w, norm_b, p_hln, DIM);

    // 2. xz = h @ in_proj_w^T   [8192, 2048] K=512
    {
        dim3 grid(2 * D_INNER / 128, NROWS / 128);
        sgemm_kernel<128, 8, EPI_NONE><<<grid, 256>>>(p_hln, DIM, in_proj_w,
                                                      nullptr, nullptr, p_xz,
                                                      NROWS, 2 * D_INNER, DIM);
    }

    // 3. xconv = silu(depthwise_conv(xm))
    conv_silu_kernel<<<(NROWS * D_INNER) / 256, 256>>>(conv_w, conv_b);

    // 4. x_dbl = xconv @ x_proj_w^T   [8192, 64] K=1024
    {
        dim3 grid(XDBL / 64, NROWS / 128);
        sgemm_kernel<64, 4, EPI_NONE><<<grid, 256>>>(p_xconv, D_INNER, x_proj_w,
                                                     nullptr, nullptr, p_xdbl,
                                                     NROWS, XDBL, D_INNER);
    }

    // 5. delta = softplus(dt @ dt_proj_w^T + dt_proj_b)   [8192, 1024] K=32
    {
        dim3 grid(D_INNER / 128, NROWS / 128);
        sgemm_kernel<128, 8, EPI_SOFTPL><<<grid, 256>>>(p_xdbl, XDBL, dt_proj_w,
                                                        dt_proj_b, nullptr, p_delta,
                                                        NROWS, D_INNER, DT_RANK);
    }

    // 6. selective scan (fused + u*D, * silu(z))
    scan_kernel<<<BATCH * (D_INNER / 16), 256>>>(A_log, Dv);

    // 7. h_out = y @ mix_out_w^T   [8192, 512] K=1024
    {
        dim3 grid(DIM / 128, NROWS / 128);
        sgemm_kernel<128, 8, EPI_NONE><<<grid, 256>>>(p_yscan, D_INNER, mix_out_w,
                                                      nullptr, nullptr, p_hout,
                                                      NROWS, DIM, D_INNER);
    }

    // 8. match_pre = residual + h_out @ match_w^T + match_b  [8192,512] K=512
    {
        dim3 grid(DIM / 128, NROWS / 128);
        sgemm_kernel<128, 8, EPI_RESID><<<grid, 256>>>(p_hout, DIM, match_w,
                                                       match_b, x, p_match,
                                                       NROWS, DIM, DIM);
    }

    // 9. geom_pre = h_out @ geom_w^T + geom_b   [8192,256] K=512
    {
        dim3 grid(D_GEOM / 128, NROWS / 128);
        sgemm_kernel<128, 8, EPI_BIAS><<<grid, 256>>>(p_hout, DIM, geom_w,
                                                      geom_b, nullptr, p_geom,
                                                      NROWS, D_GEOM, DIM);
    }

    // 10/11. final layernorms into d_out
    layernorm_kernel<<<NROWS, 256>>>(p_match, normm_w, normm_b, out_match, DIM);
    layernorm_kernel<<<NROWS, 256>>>(p_geom,  normg_w, normg_b, out_geom,  D_GEOM);
}

// round 3
// speedup vs baseline: 1.2697x; 1.1530x over previous
#include <cuda_runtime.h>
#include <cuda_bf16.h>
#include <cstdint>

// ---------------- problem constants ----------------
#define BATCH   4
#define LSEQ    2048
#define NROWS   (BATCH*LSEQ)        // 8192
#define DIM     512
#define D_INNER 1024
#define D_STATE 16
#define D_CONV  4
#define DT_RANK 32
#define XDBL    (DT_RANK + 2*D_STATE)  // 64
#define D_GEOM  256
#define EPSV    1e-5f

// ---------------- scratch (device globals; no allocation) ----------------
__device__ float g_hln  [NROWS * DIM];
__device__ float g_xz   [NROWS * 2 * D_INNER];
__device__ float g_xconv[NROWS * D_INNER];
__device__ float g_xdbl [NROWS * XDBL];
__device__ float g_delta[NROWS * D_INNER];
__device__ float g_yscan[NROWS * D_INNER];
__device__ float g_hout [NROWS * DIM];
__device__ float g_match[NROWS * DIM];
__device__ float g_geom [NROWS * D_GEOM];

// ---------------- layernorm ----------------
__global__ void layernorm_kernel(const float* __restrict__ in,
                                 const float* __restrict__ w,
                                 const float* __restrict__ b,
                                 float* __restrict__ out, int cols)
{
    int row = blockIdx.x;
    const float* p = in + (size_t)row * cols;
    float s = 0.f, sq = 0.f;
    for (int c = threadIdx.x; c < cols; c += blockDim.x) {
        float v = p[c]; s += v; sq += v * v;
    }
    int lane = threadIdx.x & 31, wid = threadIdx.x >> 5;
    #pragma unroll
    for (int o = 16; o; o >>= 1) {
        s  += __shfl_xor_sync(0xffffffffu, s,  o);
        sq += __shfl_xor_sync(0xffffffffu, sq, o);
    }
    __shared__ float shs[8], shq[8];
    if (!lane) { shs[wid] = s; shq[wid] = sq; }
    __syncthreads();
    if (threadIdx.x == 0) {
        float ts = 0.f, tq = 0.f;
        int nw = (blockDim.x + 31) >> 5;
        for (int i = 0; i < nw; i++) { ts += shs[i]; tq += shq[i]; }
        float mu  = ts / cols;
        float var = tq / cols - mu * mu;
        shs[0] = mu;
        shq[0] = rsqrtf(var + EPSV);
    }
    __syncthreads();
    float mu = shs[0], inv = shq[0];
    float* o = out + (size_t)row * cols;
    for (int c = threadIdx.x; c < cols; c += blockDim.x)
        o[c] = (p[c] - mu) * inv * w[c] + b[c];
}

// ---------------- tf32 tensor-core GEMM ----------------
// C[M,N] = A[M,K] * B[N,K]^T  (both row-major; B is a weight [N,K])
// CTA tile 128 x BN, BK=16, 256 threads = 8 warps as 4(m) x 2(n).
// Warp tile: 32 x (BN/2) via m16n8k8 tf32 mma.
#define EPI_NONE     0
#define EPI_SOFTPL   1
#define EPI_RESID    2
#define EPI_BIAS     3

__device__ __forceinline__ uint32_t f2tf(float f) {
    uint32_t r; asm("cvt.rna.tf32.f32 %0, %1;" : "=r"(r) : "f"(f)); return r;
}

__device__ __forceinline__ void mma_tf32(float* c, const uint32_t* a,
                                         uint32_t b0, uint32_t b1) {
    asm volatile(
        "mma.sync.aligned.m16n8k8.row.col.f32.tf32.tf32.f32 "
        "{%0,%1,%2,%3}, {%4,%5,%6,%7}, {%8,%9}, {%0,%1,%2,%3};"
        : "+f"(c[0]), "+f"(c[1]), "+f"(c[2]), "+f"(c[3])
        : "r"(a[0]), "r"(a[1]), "r"(a[2]), "r"(a[3]), "r"(b0), "r"(b1));
}

template<int BN, int EPI>
__global__ __launch_bounds__(256, 1)
void tgemm_kernel(const float* __restrict__ A, int lda,
                  const float* __restrict__ B,
                  const float* __restrict__ bias,
                  const float* __restrict__ resid,
                  float* __restrict__ C,
                  int M, int N, int K)
{
    const int BM = 128, BK = 16, LD = BK + 4;   // padded smem pitch
    const int WN = BN / 16;                     // n8-fragments per warp

    __shared__ uint32_t As[BM * LD];
    __shared__ uint32_t Bs[BN * LD];

    const int tid  = threadIdx.x;
    const int bm   = blockIdx.y * BM;
    const int bn   = blockIdx.x * BN;
    const int wid  = tid >> 5;
    const int lane = tid & 31;
    const int gid  = lane >> 2;       // 0..7
    const int tig  = lane & 3;        // 0..3
    const int wm   = (wid & 3) * 32;  // warp m offset in tile
    const int wn   = (wid >> 2) * (BN / 2);  // warp n offset in tile

    // loaders: each thread handles float4s at (lrow, lkc)
    const int lrow = tid >> 2;            // 0..63
    const int lkc  = (tid & 3) << 2;      // 0,4,8,12

    const float* Ap0 = A + (size_t)(bm + lrow)      * lda + lkc;
    const float* Ap1 = A + (size_t)(bm + 64 + lrow) * lda + lkc;
    const float* Bp0 = B + (size_t)(bn + lrow)      * K   + lkc;
    const float* Bp1 = (BN == 128) ? (B + (size_t)(bn + 64 + lrow) * K + lkc) : Bp0;

    float4 fa0 = *reinterpret_cast<const float4*>(Ap0);
    float4 fa1 = *reinterpret_cast<const float4*>(Ap1);
    float4 fb0 = *reinterpret_cast<const float4*>(Bp0);
    float4 fb1 = (BN == 128) ? *reinterpret_cast<const float4*>(Bp1)
                             : make_float4(0.f, 0.f, 0.f, 0.f);

    float acc[2][WN][4];
    #pragma unroll
    for (int i = 0; i < 2; i++)
        #pragma unroll
        for (int f = 0; f < WN; f++)
            #pragma unroll
            for (int j = 0; j < 4; j++)
                acc[i][f][j] = 0.f;

    for (int k0 = 0; k0 < K; k0 += BK) {
        // convert + store staged tiles
        {
            uint32_t* pa0 = &As[lrow * LD + lkc];
            pa0[0] = f2tf(fa0.x); pa0[1] = f2tf(fa0.y);
            pa0[2] = f2tf(fa0.z); pa0[3] = f2tf(fa0.w);
            uint32_t* pa1 = &As[(64 + lrow) * LD + lkc];
            pa1[0] = f2tf(fa1.x); pa1[1] = f2tf(fa1.y);
            pa1[2] = f2tf(fa1.z); pa1[3] = f2tf(fa1.w);
            uint32_t* pb0 = &Bs[lrow * LD + lkc];
            pb0[0] = f2tf(fb0.x); pb0[1] = f2tf(fb0.y);
            pb0[2] = f2tf(fb0.z); pb0[3] = f2tf(fb0.w);
            if (BN == 128) {
                uint32_t* pb1 = &Bs[(64 + lrow) * LD + lkc];
                pb1[0] = f2tf(fb1.x); pb1[1] = f2tf(fb1.y);
                pb1[2] = f2tf(fb1.z); pb1[3] = f2tf(fb1.w);
            }
        }
        __syncthreads();

        // register prefetch of next k-slab
        if (k0 + BK < K) {
            fa0 = *reinterpret_cast<const float4*>(Ap0 + k0 + BK);
            fa1 = *reinterpret_cast<const float4*>(Ap1 + k0 + BK);
            fb0 = *reinterpret_cast<const float4*>(Bp0 + k0 + BK);
            if (BN == 128)
                fb1 = *reinterpret_cast<const float4*>(Bp1 + k0 + BK);
        }

        #pragma unroll
        for (int kk = 0; kk < BK; kk += 8) {
            uint32_t af[2][4];
            #pragma unroll
            for (int i = 0; i < 2; i++) {
                int mb = wm + i * 16;
                af[i][0] = As[(mb + gid)     * LD + kk + tig];
                af[i][1] = As[(mb + gid + 8) * LD + kk + tig];
                af[i][2] = As[(mb + gid)     * LD + kk + tig + 4];
                af[i][3] = As[(mb + gid + 8) * LD + kk + tig + 4];
            }
            #pragma unroll
            for (int f = 0; f < WN; f++) {
                uint32_t b0 = Bs[(wn + f * 8 + gid) * LD + kk + tig];
                uint32_t b1 = Bs[(wn + f * 8 + gid) * LD + kk + tig + 4];
                mma_tf32(acc[0][f], af[0], b0, b1);
                mma_tf32(acc[1][f], af[1], b0, b1);
            }
        }
        __syncthreads();
    }

    // ---- epilogue ----
    #pragma unroll
    for (int i = 0; i < 2; i++) {
        int rbase = bm + wm + i * 16 + gid;
        #pragma unroll
        for (int rr = 0; rr < 2; rr++) {
            int row = rbase + rr * 8;
            float* crow = C + (size_t)row * N;
            const float* rrow = (EPI == EPI_RESID) ? (resid + (size_t)row * N) : nullptr;
            #pragma unroll
            for (int f = 0; f < WN; f++) {
                int col = bn + wn + f * 8 + 2 * tig;
                float v0 = acc[i][f][rr * 2 + 0];
                float v1 = acc[i][f][rr * 2 + 1];
                if (EPI == EPI_SOFTPL) {
                    v0 += bias[col];     v1 += bias[col + 1];
                    v0 = (v0 > 20.f) ? v0 : log1pf(__expf(v0));
                    v1 = (v1 > 20.f) ? v1 : log1pf(__expf(v1));
                } else if (EPI == EPI_RESID) {
                    v0 += bias[col]     + rrow[col];
                    v1 += bias[col + 1] + rrow[col + 1];
                } else if (EPI == EPI_BIAS) {
                    v0 += bias[col]; v1 += bias[col + 1];
                }
                *reinterpret_cast<float2*>(&crow[col]) = make_float2(v0, v1);
            }
        }
    }
}

// ---------------- depthwise causal conv + silu ----------------
__global__ void conv_silu_kernel(const float* __restrict__ conv_w,
                                 const float* __restrict__ conv_b)
{
    int idx = blockIdx.x * blockDim.x + threadIdx.x;
    if (idx >= NROWS * D_INNER) return;
    int d   = idx & (D_INNER - 1);
    int row = idx >> 10;
    int b   = row >> 11;
    int t   = row & (LSEQ - 1);

    float w0 = conv_w[d * 4 + 0], w1 = conv_w[d * 4 + 1];
    float w2 = conv_w[d * 4 + 2], w3 = conv_w[d * 4 + 3];
    const float* base = g_xz + (size_t)(b * LSEQ) * (2 * D_INNER) + d;
    float acc = conv_b[d];
    if (t >= 3) acc = fmaf(base[(size_t)(t - 3) * 2048], w0, acc);
    if (t >= 2) acc = fmaf(base[(size_t)(t - 2) * 2048], w1, acc);
    if (t >= 1) acc = fmaf(base[(size_t)(t - 1) * 2048], w2, acc);
    acc = fmaf(base[(size_t)t * 2048], w3, acc);
    float s = acc / (1.f + __expf(-acc));
    g_xconv[(size_t)row * D_INNER + d] = s;
}

// ---------------- selective scan (fused +u*D and *silu(z)) ----------------
__global__ __launch_bounds__(256)
void scan_kernel(const float* __restrict__ A_log,
                 const float* __restrict__ Dv)
{
    int b  = blockIdx.x >> 6;
    int d0 = (blockIdx.x & 63) << 4;
    int n  = threadIdx.x & 15;
    int ch = threadIdx.x >> 4;
    int d  = d0 + ch;

    float Av = -__expf(A_log[d * D_STATE + n]);
    float Dd = Dv[d];

    const float* deltaP = g_delta + (size_t)(b * LSEQ) * D_INNER + d;
    const float* uP     = g_xconv + (size_t)(b * LSEQ) * D_INNER + d;
    const float* xdP    = g_xdbl  + (size_t)(b * LSEQ) * XDBL;
    const float* zP     = g_xz    + (size_t)(b * LSEQ) * (2 * D_INNER) + D_INNER + d;
    float*       yP     = g_yscan + (size_t)(b * LSEQ) * D_INNER + d;

    float h = 0.f;
    #pragma unroll 4
    for (int t = 0; t < LSEQ; t++) {
        float dlt = deltaP[(size_t)t * D_INNER];
        float uu  = uP[(size_t)t * D_INNER];
        float Bv  = xdP[(size_t)t * XDBL + DT_RANK + n];
        float Cv  = xdP[(size_t)t * XDBL + DT_RANK + D_STATE + n];
        float dA  = __expf(dlt * Av);
        h = fmaf(dA, h, dlt * uu * Bv);
        float p = h * Cv;
        #pragma unroll
        for (int o = 8; o; o >>= 1)
            p += __shfl_xor_sync(0xffffffffu, p, o);
        if (n == 0) {
            float z = zP[(size_t)t * (2 * D_INNER)];
            float sig = z / (1.f + __expf(-z));
            yP[(size_t)t * D_INNER] = (p + uu * Dd) * sig;
        }
    }
}

// ---------------- launch ----------------
static float* sym(const void* symbol) {
    void* p = nullptr;
    cudaGetSymbolAddress(&p, symbol);
    return (float*)p;
}

extern "C" void kernel_launch(void* const* d_in, const int* in_sizes, int n_in,
                              void* d_out, int out_size)
{
    const float* x         = (const float*)d_in[0];
    const float* norm_w    = (const float*)d_in[1];
    const float* norm_b    = (const float*)d_in[2];
    const float* in_proj_w = (const float*)d_in[3];
    const float* conv_w    = (const float*)d_in[4];
    const float* conv_b    = (const float*)d_in[5];
    const float* x_proj_w  = (const float*)d_in[6];
    const float* dt_proj_w = (const float*)d_in[7];
    const float* dt_proj_b = (const float*)d_in[8];
    const float* A_log     = (const float*)d_in[9];
    const float* Dv        = (const float*)d_in[10];
    const float* mix_out_w = (const float*)d_in[11];
    const float* match_w   = (const float*)d_in[12];
    const float* match_b   = (const float*)d_in[13];
    const float* geom_w    = (const float*)d_in[14];
    const float* geom_b    = (const float*)d_in[15];
    const float* normm_w   = (const float*)d_in[16];
    const float* normm_b   = (const float*)d_in[17];
    const float* normg_w   = (const float*)d_in[18];
    const float* normg_b   = (const float*)d_in[19];

    float* p_hln   = sym(g_hln);
    float* p_xz    = sym(g_xz);
    float* p_xconv = sym(g_xconv);
    float* p_xdbl  = sym(g_xdbl);
    float* p_delta = sym(g_delta);
    float* p_yscan = sym(g_yscan);
    float* p_hout  = sym(g_hout);
    float* p_match = sym(g_match);
    float* p_geom  = sym(g_geom);

    float* out_match = (float*)d_out;
    float* out_geom  = (float*)d_out + (size_t)NROWS * DIM;

    // 1. h = layernorm(x)
    layernorm_kernel<<<NROWS, 256>>>(x, norm_w, norm_b, p_hln, DIM);

    // 2. xz = h @ in_proj_w^T   [8192, 2048] K=512
    {
        dim3 grid(2 * D_INNER / 128, NROWS / 128);
        tgemm_kernel<128, EPI_NONE><<<grid, 256>>>(p_hln, DIM, in_proj_w,
                                                   nullptr, nullptr, p_xz,
                                                   NROWS, 2 * D_INNER, DIM);
    }

    // 3. xconv = silu(depthwise_conv(xm))
    conv_silu_kernel<<<(NROWS * D_INNER) / 256, 256>>>(conv_w, conv_b);

    // 4. x_dbl = xconv @ x_proj_w^T   [8192, 64] K=1024
    {
        dim3 grid(XDBL / 64, NROWS / 128);
        tgemm_kernel<64, EPI_NONE><<<grid, 256>>>(p_xconv, D_INNER, x_proj_w,
                                                  nullptr, nullptr, p_xdbl,
                                                  NROWS, XDBL, D_INNER);
    }

    // 5. delta = softplus(dt @ dt_proj_w^T + dt_proj_b)   [8192, 1024] K=32
    {
        dim3 grid(D_INNER / 128, NROWS / 128);
        tgemm_kernel<128, EPI_SOFTPL><<<grid, 256>>>(p_xdbl, XDBL, dt_proj_w,
                                                     dt_proj_b, nullptr, p_delta,
                                                     NROWS, D_INNER, DT_RANK);
    }

    // 6. selective scan (fused + u*D, * silu(z))
    scan_kernel<<<BATCH * (D_INNER / 16), 256>>>(A_log, Dv);

    // 7. h_out = y @ mix_out_w^T   [8192, 512] K=1024
    {
        dim3 grid(DIM / 128, NROWS / 128);
        tgemm_kernel<128, EPI_NONE><<<grid, 256>>>(p_yscan, D_INNER, mix_out_w,
                                                   nullptr, nullptr, p_hout,
                                                   NROWS, DIM, D_INNER);
    }

    // 8. match_pre = residual + h_out @ match_w^T + match_b  [8192,512] K=512
    {
        dim3 grid(DIM / 128, NROWS / 128);
        tgemm_kernel<128, EPI_RESID><<<grid, 256>>>(p_hout, DIM, match_w,
                                                    match_b, x, p_match,
                                                    NROWS, DIM, DIM);
    }

    // 9. geom_pre = h_out @ geom_w^T + geom_b   [8192,256] K=512
    {
        dim3 grid(D_GEOM / 128, NROWS / 128);
        tgemm_kernel<128, EPI_BIAS><<<grid, 256>>>(p_hout, DIM, geom_w,
                                                   geom_b, nullptr, p_geom,
                                                   NROWS, D_GEOM, DIM);
    }

    // 10/11. final layernorms into d_out
    layernorm_kernel<<<NROWS, 256>>>(p_match, normm_w, normm_b, out_match, DIM);
    layernorm_kernel<<<NROWS, 256>>>(p_geom,  normg_w, normg_b, out_geom,  D_GEOM);
}

// round 4
// speedup vs baseline: 1.3201x; 1.0398x over previous
#include <cuda_runtime.h>
#include <cuda_bf16.h>
#include <cstdint>

// ---------------- problem constants ----------------
#define BATCH   4
#define LSEQ    2048
#define NROWS   (BATCH*LSEQ)        // 8192
#define DIM     512
#define D_INNER 1024
#define D_STATE 16
#define D_CONV  4
#define DT_RANK 32
#define XDBL    (DT_RANK + 2*D_STATE)  // 64
#define D_GEOM  256
#define EPSV    1e-5f

// ---------------- scratch (device globals; no allocation) ----------------
__device__ float g_hln  [NROWS * DIM];
__device__ float g_xz   [NROWS * 2 * D_INNER];
__device__ float g_xconv[NROWS * D_INNER];
__device__ float g_xdbl [NROWS * XDBL];
__device__ float g_delta[NROWS * D_INNER];
__device__ float g_yscan[NROWS * D_INNER];
__device__ float g_hout [NROWS * DIM];
__device__ float g_match[NROWS * DIM];
__device__ float g_geom [NROWS * D_GEOM];

// ---------------- layernorm ----------------
__global__ void layernorm_kernel(const float* __restrict__ in,
                                 const float* __restrict__ w,
                                 const float* __restrict__ b,
                                 float* __restrict__ out, int cols)
{
    int row = blockIdx.x;
    const float* p = in + (size_t)row * cols;
    float s = 0.f, sq = 0.f;
    for (int c = threadIdx.x; c < cols; c += blockDim.x) {
        float v = p[c]; s += v; sq += v * v;
    }
    int lane = threadIdx.x & 31, wid = threadIdx.x >> 5;
    #pragma unroll
    for (int o = 16; o; o >>= 1) {
        s  += __shfl_xor_sync(0xffffffffu, s,  o);
        sq += __shfl_xor_sync(0xffffffffu, sq, o);
    }
    __shared__ float shs[8], shq[8];
    if (!lane) { shs[wid] = s; shq[wid] = sq; }
    __syncthreads();
    if (threadIdx.x == 0) {
        float ts = 0.f, tq = 0.f;
        int nw = (blockDim.x + 31) >> 5;
        for (int i = 0; i < nw; i++) { ts += shs[i]; tq += shq[i]; }
        float mu  = ts / cols;
        float var = tq / cols - mu * mu;
        shs[0] = mu;
        shq[0] = rsqrtf(var + EPSV);
    }
    __syncthreads();
    float mu = shs[0], inv = shq[0];
    float* o = out + (size_t)row * cols;
    for (int c = threadIdx.x; c < cols; c += blockDim.x)
        o[c] = (p[c] - mu) * inv * w[c] + b[c];
}

// ---------------- tf32 tensor-core GEMM (double-buffered) ----------------
// C[M,N] = A[M,K] * B[N,K]^T (row-major; B is weight [N,K])
// CTA tile 128 x BN, BK=16, 256 thr = 8 warps (4m x 2n), warp tile 32 x BN/2.
// KSPLIT>1: gridDim.z slices K; epilogue atomicAdd (C must be pre-zeroed);
// bias applied only by z==0.
#define EPI_NONE     0
#define EPI_SOFTPL   1
#define EPI_RESID    2
#define EPI_BIAS     3

__device__ __forceinline__ uint32_t f2tf(float f) {
    uint32_t r; asm("cvt.rna.tf32.f32 %0, %1;" : "=r"(r) : "f"(f)); return r;
}

__device__ __forceinline__ void mma_tf32(float* c, const uint32_t* a,
                                         uint32_t b0, uint32_t b1) {
    asm volatile(
        "mma.sync.aligned.m16n8k8.row.col.f32.tf32.tf32.f32 "
        "{%0,%1,%2,%3}, {%4,%5,%6,%7}, {%8,%9}, {%0,%1,%2,%3};"
        : "+f"(c[0]), "+f"(c[1]), "+f"(c[2]), "+f"(c[3])
        : "r"(a[0]), "r"(a[1]), "r"(a[2]), "r"(a[3]), "r"(b0), "r"(b1));
}

template<int BN, int EPI, int KSPLIT>
__global__ __launch_bounds__(256, 2)
void tgemm_kernel(const float* __restrict__ A, int lda,
                  const float* __restrict__ B,
                  const float* __restrict__ bias,
                  const float* __restrict__ resid,
                  float* __restrict__ C,
                  int M, int N, int K)
{
    const int BM = 128, BK = 16, LD = BK + 4;
    const int WN = BN / 16;

    __shared__ uint32_t As[2][BM * LD];
    __shared__ uint32_t Bs[2][BN * LD];

    const int tid  = threadIdx.x;
    const int bm   = blockIdx.y * BM;
    const int bn   = blockIdx.x * BN;
    const int wid  = tid >> 5;
    const int lane = tid & 31;
    const int gid  = lane >> 2;
    const int tig  = lane & 3;
    const int wm   = (wid & 3) * 32;
    const int wn   = (wid >> 2) * (BN / 2);

    const int lrow = tid >> 2;            // 0..63
    const int lkc  = (tid & 3) << 2;      // 0,4,8,12

    const int kchunk = K / KSPLIT;
    const int kbeg   = blockIdx.z * kchunk;
    const int kend   = kbeg + kchunk;

    const float* Ap0 = A + (size_t)(bm + lrow)      * lda + lkc;
    const float* Ap1 = A + (size_t)(bm + 64 + lrow) * lda + lkc;
    const float* Bp0 = B + (size_t)(bn + lrow)      * K   + lkc;
    const float* Bp1 = B + (size_t)(bn + ((BN == 128) ? 64 : 0) + lrow) * K + lkc;

    float4 fa0 = *reinterpret_cast<const float4*>(Ap0 + kbeg);
    float4 fa1 = *reinterpret_cast<const float4*>(Ap1 + kbeg);
    float4 fb0 = *reinterpret_cast<const float4*>(Bp0 + kbeg);
    float4 fb1 = make_float4(0.f, 0.f, 0.f, 0.f);
    if (BN == 128) fb1 = *reinterpret_cast<const float4*>(Bp1 + kbeg);

    float acc[2][WN][4];
    #pragma unroll
    for (int i = 0; i < 2; i++)
        #pragma unroll
        for (int f = 0; f < WN; f++)
            #pragma unroll
            for (int j = 0; j < 4; j++)
                acc[i][f][j] = 0.f;

    auto stage = [&](int s) {
        uint32_t* pa0 = &As[s][lrow * LD + lkc];
        pa0[0] = f2tf(fa0.x); pa0[1] = f2tf(fa0.y);
        pa0[2] = f2tf(fa0.z); pa0[3] = f2tf(fa0.w);
        uint32_t* pa1 = &As[s][(64 + lrow) * LD + lkc];
        pa1[0] = f2tf(fa1.x); pa1[1] = f2tf(fa1.y);
        pa1[2] = f2tf(fa1.z); pa1[3] = f2tf(fa1.w);
        uint32_t* pb0 = &Bs[s][lrow * LD + lkc];
        pb0[0] = f2tf(fb0.x); pb0[1] = f2tf(fb0.y);
        pb0[2] = f2tf(fb0.z); pb0[3] = f2tf(fb0.w);
        if (BN == 128) {
            uint32_t* pb1 = &Bs[s][(64 + lrow) * LD + lkc];
            pb1[0] = f2tf(fb1.x); pb1[1] = f2tf(fb1.y);
            pb1[2] = f2tf(fb1.z); pb1[3] = f2tf(fb1.w);
        }
    };

    stage(0);
    __syncthreads();

    int s = 0;
    for (int k0 = kbeg; k0 < kend; k0 += BK) {
        const bool more = (k0 + BK) < kend;
        if (more) {
            fa0 = *reinterpret_cast<const float4*>(Ap0 + k0 + BK);
            fa1 = *reinterpret_cast<const float4*>(Ap1 + k0 + BK);
            fb0 = *reinterpret_cast<const float4*>(Bp0 + k0 + BK);
            if (BN == 128)
                fb1 = *reinterpret_cast<const float4*>(Bp1 + k0 + BK);
        }

        #pragma unroll
        for (int kk = 0; kk < BK; kk += 8) {
            uint32_t af[2][4];
            #pragma unroll
            for (int i = 0; i < 2; i++) {
                int mb = wm + i * 16;
                af[i][0] = As[s][(mb + gid)     * LD + kk + tig];
                af[i][1] = As[s][(mb + gid + 8) * LD + kk + tig];
                af[i][2] = As[s][(mb + gid)     * LD + kk + tig + 4];
                af[i][3] = As[s][(mb + gid + 8) * LD + kk + tig + 4];
            }
            #pragma unroll
            for (int f = 0; f < WN; f++) {
                uint32_t b0 = Bs[s][(wn + f * 8 + gid) * LD + kk + tig];
                uint32_t b1 = Bs[s][(wn + f * 8 + gid) * LD + kk + tig + 4];
                mma_tf32(acc[0][f], af[0], b0, b1);
                mma_tf32(acc[1][f], af[1], b0, b1);
            }
        }

        if (more) stage(s ^ 1);
        s ^= 1;
        __syncthreads();
    }

    // ---- epilogue ----
    #pragma unroll
    for (int i = 0; i < 2; i++) {
        #pragma unroll
        for (int rr = 0; rr < 2; rr++) {
            int row = bm + wm + i * 16 + gid + rr * 8;
            float* crow = C + (size_t)row * N;
            const float* rrow = (EPI == EPI_RESID) ? (resid + (size_t)row * N) : nullptr;
            #pragma unroll
            for (int f = 0; f < WN; f++) {
                int col = bn + wn + f * 8 + 2 * tig;
                float v0 = acc[i][f][rr * 2 + 0];
                float v1 = acc[i][f][rr * 2 + 1];
                if (KSPLIT > 1) {
                    if (EPI == EPI_BIAS && blockIdx.z == 0) {
                        v0 += bias[col]; v1 += bias[col + 1];
                    }
                    atomicAdd(&crow[col],     v0);
                    atomicAdd(&crow[col + 1], v1);
                } else {
                    if (EPI == EPI_SOFTPL) {
                        v0 += bias[col];     v1 += bias[col + 1];
                        v0 = (v0 > 20.f) ? v0 : log1pf(__expf(v0));
                        v1 = (v1 > 20.f) ? v1 : log1pf(__expf(v1));
                    } else if (EPI == EPI_RESID) {
                        v0 += bias[col]     + rrow[col];
                        v1 += bias[col + 1] + rrow[col + 1];
                    } else if (EPI == EPI_BIAS) {
                        v0 += bias[col]; v1 += bias[col + 1];
                    }
                    *reinterpret_cast<float2*>(&crow[col]) = make_float2(v0, v1);
                }
            }
        }
    }
}

// ---------------- depthwise causal conv + silu ----------------
__global__ void conv_silu_kernel(const float* __restrict__ conv_w,
                                 const float* __restrict__ conv_b)
{
    int idx = blockIdx.x * blockDim.x + threadIdx.x;
    if (idx >= NROWS * D_INNER) return;
    int d   = idx & (D_INNER - 1);
    int row = idx >> 10;
    int b   = row >> 11;
    int t   = row & (LSEQ - 1);

    float w0 = conv_w[d * 4 + 0], w1 = conv_w[d * 4 + 1];
    float w2 = conv_w[d * 4 + 2], w3 = conv_w[d * 4 + 3];
    const float* base = g_xz + (size_t)(b * LSEQ) * (2 * D_INNER) + d;
    float acc = conv_b[d];
    if (t >= 3) acc = fmaf(base[(size_t)(t - 3) * 2048], w0, acc);
    if (t >= 2) acc = fmaf(base[(size_t)(t - 2) * 2048], w1, acc);
    if (t >= 1) acc = fmaf(base[(size_t)(t - 1) * 2048], w2, acc);
    acc = fmaf(base[(size_t)t * 2048], w3, acc);
    float s = acc / (1.f + __expf(-acc));
    g_xconv[(size_t)row * D_INNER + d] = s;
}

// ---------------- selective scan (fused +u*D and *silu(z)) ----------------
__global__ __launch_bounds__(256)
void scan_kernel(const float* __restrict__ A_log,
                 const float* __restrict__ Dv)
{
    int b  = blockIdx.x >> 6;
    int d0 = (blockIdx.x & 63) << 4;
    int n  = threadIdx.x & 15;
    int ch = threadIdx.x >> 4;
    int d  = d0 + ch;

    float Av = -__expf(A_log[d * D_STATE + n]);
    float Dd = Dv[d];

    const float* deltaP = g_delta + (size_t)(b * LSEQ) * D_INNER + d;
    const float* uP     = g_xconv + (size_t)(b * LSEQ) * D_INNER + d;
    const float* xdP    = g_xdbl  + (size_t)(b * LSEQ) * XDBL;
    const float* zP     = g_xz    + (size_t)(b * LSEQ) * (2 * D_INNER) + D_INNER + d;
    float*       yP     = g_yscan + (size_t)(b * LSEQ) * D_INNER + d;

    float h = 0.f;
    #pragma unroll 4
    for (int t = 0; t < LSEQ; t++) {
        float dlt = deltaP[(size_t)t * D_INNER];
        float uu  = uP[(size_t)t * D_INNER];
        float Bv  = xdP[(size_t)t * XDBL + DT_RANK + n];
        float Cv  = xdP[(size_t)t * XDBL + DT_RANK + D_STATE + n];
        float dA  = __expf(dlt * Av);
        h = fmaf(dA, h, dlt * uu * Bv);
        float p = h * Cv;
        #pragma unroll
        for (int o = 8; o; o >>= 1)
            p += __shfl_xor_sync(0xffffffffu, p, o);
        if (n == 0) {
            float z = zP[(size_t)t * (2 * D_INNER)];
            float sig = z / (1.f + __expf(-z));
            yP[(size_t)t * D_INNER] = (p + uu * Dd) * sig;
        }
    }
}

// ---------------- launch ----------------
static float* sym(const void* symbol) {
    void* p = nullptr;
    cudaGetSymbolAddress(&p, symbol);
    return (float*)p;
}

extern "C" void kernel_launch(void* const* d_in, const int* in_sizes, int n_in,
                              void* d_out, int out_size)
{
    const float* x         = (const float*)d_in[0];
    const float* norm_w    = (const float*)d_in[1];
    const float* norm_b    = (const float*)d_in[2];
    const float* in_proj_w = (const float*)d_in[3];
    const float* conv_w    = (const float*)d_in[4];
    const float* conv_b    = (const float*)d_in[5];
    const float* x_proj_w  = (const float*)d_in[6];
    const float* dt_proj_w = (const float*)d_in[7];
    const float* dt_proj_b = (const float*)d_in[8];
    const float* A_log     = (const float*)d_in[9];
    const float* Dv        = (const float*)d_in[10];
    const float* mix_out_w = (const float*)d_in[11];
    const float* match_w   = (const float*)d_in[12];
    const float* match_b   = (const float*)d_in[13];
    const float* geom_w    = (const float*)d_in[14];
    const float* geom_b    = (const float*)d_in[15];
    const float* normm_w   = (const float*)d_in[16];
    const float* normm_b   = (const float*)d_in[17];
    const float* normg_w   = (const float*)d_in[18];
    const float* normg_b   = (const float*)d_in[19];

    float* p_hln   = sym(g_hln);
    float* p_xz    = sym(g_xz);
    float* p_xconv = sym(g_xconv);
    float* p_xdbl  = sym(g_xdbl);
    float* p_delta = sym(g_delta);
    float* p_yscan = sym(g_yscan);
    float* p_hout  = sym(g_hout);
    float* p_match = sym(g_match);
    float* p_geom  = sym(g_geom);

    float* out_match = (float*)d_out;
    float* out_geom  = (float*)d_out + (size_t)NROWS * DIM;

    // 1. h = layernorm(x)
    layernorm_kernel<<<NROWS, 256>>>(x, norm_w, norm_b, p_hln, DIM);

    // 2. xz = h @ in_proj_w^T   [8192, 2048] K=512  (1024 CTAs)
    {
        dim3 grid(2 * D_INNER / 128, NROWS / 128);
        tgemm_kernel<128, EPI_NONE, 1><<<grid, 256>>>(p_hln, DIM, in_proj_w,
                                                      nullptr, nullptr, p_xz,
                                                      NROWS, 2 * D_INNER, DIM);
    }

    // 3. xconv = silu(depthwise_conv(xm))
    conv_silu_kernel<<<(NROWS * D_INNER) / 256, 256>>>(conv_w, conv_b);

    // 4. x_dbl = xconv @ x_proj_w^T  [8192, 64] K=1024, split-K=4 (256 CTAs)
    cudaMemsetAsync(p_xdbl, 0, (size_t)NROWS * XDBL * sizeof(float));
    {
        dim3 grid(XDBL / 64, NROWS / 128, 4);
        tgemm_kernel<64, EPI_NONE, 4><<<grid, 256>>>(p_xconv, D_INNER, x_proj_w,
                                                     nullptr, nullptr, p_xdbl,
                                                     NROWS, XDBL, D_INNER);
    }

    // 5. delta = softplus(dt @ dt_proj_w^T + dt_proj_b) [8192,1024] K=32 (512 CTAs)
    {
        dim3 grid(D_INNER / 128, NROWS / 128);
        tgemm_kernel<128, EPI_SOFTPL, 1><<<grid, 256>>>(p_xdbl, XDBL, dt_proj_w,
                                                        dt_proj_b, nullptr, p_delta,
                                                        NROWS, D_INNER, DT_RANK);
    }

    // 6. selective scan (fused + u*D, * silu(z))
    scan_kernel<<<BATCH * (D_INNER / 16), 256>>>(A_log, Dv);

    // 7. h_out = y @ mix_out_w^T   [8192, 512] K=1024 (256 CTAs)
    {
        dim3 grid(DIM / 128, NROWS / 128);
        tgemm_kernel<128, EPI_NONE, 1><<<grid, 256>>>(p_yscan, D_INNER, mix_out_w,
                                                      nullptr, nullptr, p_hout,
                                                      NROWS, DIM, D_INNER);
    }

    // 8. match_pre = residual + h_out @ match_w^T + match_b  [8192,512] K=512
    {
        dim3 grid(DIM / 128, NROWS / 128);
        tgemm_kernel<128, EPI_RESID, 1><<<grid, 256>>>(p_hout, DIM, match_w,
                                                       match_b, x, p_match,
                                                       NROWS, DIM, DIM);
    }

    // 9. geom_pre = h_out @ geom_w^T + geom_b  [8192,256] K=512, split-K=2 (256 CTAs)
    cudaMemsetAsync(p_geom, 0, (size_t)NROWS * D_GEOM * sizeof(float));
    {
        dim3 grid(D_GEOM / 128, NROWS / 128, 2);
        tgemm_kernel<128, EPI_BIAS, 2><<<grid, 256>>>(p_hout, DIM, geom_w,
                                                      geom_b, nullptr, p_geom,
                                                      NROWS, D_GEOM, DIM);
    }

    // 10/11. final layernorms into d_out
    layernorm_kernel<<<NROWS, 256>>>(p_match, normm_w, normm_b, out_match, DIM);
    layernorm_kernel<<<NROWS, 256>>>(p_geom,  normg_w, normg_b, out_geom,  D_GEOM);
}

// round 5
// speedup vs baseline: 3.2974x; 2.4977x over previous
#include <cuda_runtime.h>
#include <cuda_bf16.h>
#include <cstdint>

// ---------------- problem constants ----------------
#define BATCH   4
#define LSEQ    2048
#define NROWS   (BATCH*LSEQ)        // 8192
#define DIM     512
#define D_INNER 1024
#define D_STATE 16
#define D_CONV  4
#define DT_RANK 32
#define XDBL    (DT_RANK + 2*D_STATE)  // 64
#define D_GEOM  256
#define EPSV    1e-5f
#define CS      16                   // scan chunks
#define TCH     (LSEQ/CS)            // 128 steps per chunk

// ---------------- scratch (device globals; no allocation) ----------------
__device__ float g_hln  [NROWS * DIM];
__device__ float g_xz   [NROWS * 2 * D_INNER];
__device__ float g_xconv[NROWS * D_INNER];         // u, [t][d]
__device__ float g_uT   [BATCH * D_INNER * LSEQ];  // u transposed [b][d][t]
__device__ float g_dT   [BATCH * D_INNER * LSEQ];  // delta transposed [b][d][t]
__device__ float g_xdbl [NROWS * XDBL];
__device__ float g_yscan[NROWS * D_INNER];
__device__ float g_hout [NROWS * DIM];
__device__ float g_match[NROWS * DIM];
__device__ float g_geom [NROWS * D_GEOM];
__device__ float g_hchk [BATCH * D_INNER * CS * D_STATE]; // [b][d][c][n]
__device__ float g_schk [BATCH * D_INNER * CS];           // [b][d][c]
__device__ float g_h0   [BATCH * D_INNER * CS * D_STATE]; // [b][d][c][n]

// ---------------- layernorm ----------------
__global__ void layernorm_kernel(const float* __restrict__ in,
                                 const float* __restrict__ w,
                                 const float* __restrict__ b,
                                 float* __restrict__ out, int cols)
{
    int row = blockIdx.x;
    const float* p = in + (size_t)row * cols;
    float s = 0.f, sq = 0.f;
    for (int c = threadIdx.x; c < cols; c += blockDim.x) {
        float v = p[c]; s += v; sq += v * v;
    }
    int lane = threadIdx.x & 31, wid = threadIdx.x >> 5;
    #pragma unroll
    for (int o = 16; o; o >>= 1) {
        s  += __shfl_xor_sync(0xffffffffu, s,  o);
        sq += __shfl_xor_sync(0xffffffffu, sq, o);
    }
    __shared__ float shs[8], shq[8];
    if (!lane) { shs[wid] = s; shq[wid] = sq; }
    __syncthreads();
    if (threadIdx.x == 0) {
        float ts = 0.f, tq = 0.f;
        int nw = (blockDim.x + 31) >> 5;
        for (int i = 0; i < nw; i++) { ts += shs[i]; tq += shq[i]; }
        float mu  = ts / cols;
        float var = tq / cols - mu * mu;
        shs[0] = mu;
        shq[0] = rsqrtf(var + EPSV);
    }
    __syncthreads();
    float mu = shs[0], inv = shq[0];
    float* o = out + (size_t)row * cols;
    for (int c = threadIdx.x; c < cols; c += blockDim.x)
        o[c] = (p[c] - mu) * inv * w[c] + b[c];
}

// ---------------- tf32 tensor-core GEMM (double-buffered) ----------------
#define EPI_NONE      0
#define EPI_SOFTPL    1
#define EPI_RESID     2
#define EPI_BIAS      3
#define EPI_SOFTPL_T  4   // softplus(acc+bias) stored transposed [b][col][t]

__device__ __forceinline__ uint32_t f2tf(float f) {
    uint32_t r; asm("cvt.rna.tf32.f32 %0, %1;" : "=r"(r) : "f"(f)); return r;
}

__device__ __forceinline__ void mma_tf32(float* c, const uint32_t* a,
                                         uint32_t b0, uint32_t b1) {
    asm volatile(
        "mma.sync.aligned.m16n8k8.row.col.f32.tf32.tf32.f32 "
        "{%0,%1,%2,%3}, {%4,%5,%6,%7}, {%8,%9}, {%0,%1,%2,%3};"
        : "+f"(c[0]), "+f"(c[1]), "+f"(c[2]), "+f"(c[3])
        : "r"(a[0]), "r"(a[1]), "r"(a[2]), "r"(a[3]), "r"(b0), "r"(b1));
}

__device__ __forceinline__ float softplusf(float v) {
    return (v > 20.f) ? v : log1pf(__expf(v));
}

template<int BN, int EPI>
__global__ __launch_bounds__(256, 2)
void tgemm_kernel(const float* __restrict__ A, int lda,
                  const float* __restrict__ B,
                  const float* __restrict__ bias,
                  const float* __restrict__ resid,
                  float* __restrict__ C,
                  int M, int N, int K)
{
    const int BM = 128, BK = 16, LD = BK + 4;
    const int WN = BN / 16;

    __shared__ uint32_t As[2][BM * LD];
    __shared__ uint32_t Bs[2][BN * LD];

    const int tid  = threadIdx.x;
    const int bm   = blockIdx.y * BM;
    const int bn   = blockIdx.x * BN;
    const int wid  = tid >> 5;
    const int lane = tid & 31;
    const int gid  = lane >> 2;
    const int tig  = lane & 3;
    const int wm   = (wid & 3) * 32;
    const int wn   = (wid >> 2) * (BN / 2);

    const int lrow = tid >> 2;
    const int lkc  = (tid & 3) << 2;

    const float* Ap0 = A + (size_t)(bm + lrow)      * lda + lkc;
    const float* Ap1 = A + (size_t)(bm + 64 + lrow) * lda + lkc;
    const float* Bp0 = B + (size_t)(bn + lrow)      * K   + lkc;
    const float* Bp1 = B + (size_t)(bn + ((BN == 128) ? 64 : 0) + lrow) * K + lkc;

    float4 fa0 = *reinterpret_cast<const float4*>(Ap0);
    float4 fa1 = *reinterpret_cast<const float4*>(Ap1);
    float4 fb0 = *reinterpret_cast<const float4*>(Bp0);
    float4 fb1 = make_float4(0.f, 0.f, 0.f, 0.f);
    if (BN == 128) fb1 = *reinterpret_cast<const float4*>(Bp1);

    float acc[2][WN][4];
    #pragma unroll
    for (int i = 0; i < 2; i++)
        #pragma unroll
        for (int f = 0; f < WN; f++)
            #pragma unroll
            for (int j = 0; j < 4; j++)
                acc[i][f][j] = 0.f;

    auto stage = [&](int s) {
        uint32_t* pa0 = &As[s][lrow * LD + lkc];
        pa0[0] = f2tf(fa0.x); pa0[1] = f2tf(fa0.y);
        pa0[2] = f2tf(fa0.z); pa0[3] = f2tf(fa0.w);
        uint32_t* pa1 = &As[s][(64 + lrow) * LD + lkc];
        pa1[0] = f2tf(fa1.x); pa1[1] = f2tf(fa1.y);
        pa1[2] = f2tf(fa1.z); pa1[3] = f2tf(fa1.w);
        uint32_t* pb0 = &Bs[s][lrow * LD + lkc];
        pb0[0] = f2tf(fb0.x); pb0[1] = f2tf(fb0.y);
        pb0[2] = f2tf(fb0.z); pb0[3] = f2tf(fb0.w);
        if (BN == 128) {
            uint32_t* pb1 = &Bs[s][(64 + lrow) * LD + lkc];
            pb1[0] = f2tf(fb1.x); pb1[1] = f2tf(fb1.y);
            pb1[2] = f2tf(fb1.z); pb1[3] = f2tf(fb1.w);
        }
    };

    stage(0);
    __syncthreads();

    int s = 0;
    for (int k0 = 0; k0 < K; k0 += BK) {
        const bool more = (k0 + BK) < K;
        if (more) {
            fa0 = *reinterpret_cast<const float4*>(Ap0 + k0 + BK);
            fa1 = *reinterpret_cast<const float4*>(Ap1 + k0 + BK);
            fb0 = *reinterpret_cast<const float4*>(Bp0 + k0 + BK);
            if (BN == 128)
                fb1 = *reinterpret_cast<const float4*>(Bp1 + k0 + BK);
        }

        #pragma unroll
        for (int kk = 0; kk < BK; kk += 8) {
            uint32_t af[2][4];
            #pragma unroll
            for (int i = 0; i < 2; i++) {
                int mb = wm + i * 16;
                af[i][0] = As[s][(mb + gid)     * LD + kk + tig];
                af[i][1] = As[s][(mb + gid + 8) * LD + kk + tig];
                af[i][2] = As[s][(mb + gid)     * LD + kk + tig + 4];
                af[i][3] = As[s][(mb + gid + 8) * LD + kk + tig + 4];
            }
            #pragma unroll
            for (int f = 0; f < WN; f++) {
                uint32_t b0 = Bs[s][(wn + f * 8 + gid) * LD + kk + tig];
                uint32_t b1 = Bs[s][(wn + f * 8 + gid) * LD + kk + tig + 4];
                mma_tf32(acc[0][f], af[0], b0, b1);
                mma_tf32(acc[1][f], af[1], b0, b1);
            }
        }

        if (more) stage(s ^ 1);
        s ^= 1;
        __syncthreads();
    }

    // ---- epilogue ----
    #pragma unroll
    for (int i = 0; i < 2; i++) {
        #pragma unroll
        for (int rr = 0; rr < 2; rr++) {
            int row = bm + wm + i * 16 + gid + rr * 8;
            float* crow = C + (size_t)row * N;
            const float* rrow = (EPI == EPI_RESID) ? (resid + (size_t)row * N) : nullptr;
            #pragma unroll
            for (int f = 0; f < WN; f++) {
                int col = bn + wn + f * 8 + 2 * tig;
                float v0 = acc[i][f][rr * 2 + 0];
                float v1 = acc[i][f][rr * 2 + 1];
                if (EPI == EPI_SOFTPL_T) {
                    // store delta transposed: [b][col][t], b=row/2048, t=row%2048
                    v0 = softplusf(v0 + bias[col]);
                    v1 = softplusf(v1 + bias[col + 1]);
                    int bb2 = row >> 11, tt = row & (LSEQ - 1);
                    C[((size_t)(bb2 * D_INNER) + col)     * LSEQ + tt] = v0;
                    C[((size_t)(bb2 * D_INNER) + col + 1) * LSEQ + tt] = v1;
                } else {
                    if (EPI == EPI_SOFTPL) {
                        v0 = softplusf(v0 + bias[col]);
                        v1 = softplusf(v1 + bias[col + 1]);
                    } else if (EPI == EPI_RESID) {
                        v0 += bias[col]     + rrow[col];
                        v1 += bias[col + 1] + rrow[col + 1];
                    } else if (EPI == EPI_BIAS) {
                        v0 += bias[col]; v1 += bias[col + 1];
                    }
                    *reinterpret_cast<float2*>(&crow[col]) = make_float2(v0, v1);
                }
            }
        }
    }
}

// ---------------- depthwise causal conv + silu, dual-layout output ----------------
// grid (LSEQ/32, D_INNER/32, B), block (32,8). Writes g_xconv [t][d] and g_uT [b][d][t].
__global__ __launch_bounds__(256)
void conv_silu_T_kernel(const float* __restrict__ conv_w,
                        const float* __restrict__ conv_b)
{
    __shared__ float sx[35][33];
    __shared__ float so[32][33];
    int t0 = blockIdx.x * 32, d0 = blockIdx.y * 32, b = blockIdx.z;
    int tx = threadIdx.x, ty = threadIdx.y;

    for (int r = ty; r < 35; r += 8) {
        int t = t0 - 3 + r;
        float v = (t >= 0) ? g_xz[((size_t)(b * LSEQ) + t) * (2 * D_INNER) + d0 + tx] : 0.f;
        sx[r][tx] = v;
    }
    __syncthreads();

    int d = d0 + tx;
    float w0 = conv_w[d * 4 + 0], w1 = conv_w[d * 4 + 1];
    float w2 = conv_w[d * 4 + 2], w3 = conv_w[d * 4 + 3];
    float bb = conv_b[d];
    for (int r = ty; r < 32; r += 8) {
        float acc = bb;
        acc = fmaf(w0, sx[r][tx],     acc);
        acc = fmaf(w1, sx[r + 1][tx], acc);
        acc = fmaf(w2, sx[r + 2][tx], acc);
        acc = fmaf(w3, sx[r + 3][tx], acc);
        float sv = acc / (1.f + __expf(-acc));
        g_xconv[((size_t)(b * LSEQ) + t0 + r) * D_INNER + d] = sv;
        so[tx][r] = sv;
    }
    __syncthreads();

    for (int r = ty; r < 32; r += 8)
        g_uT[((size_t)(b * D_INNER) + d0 + r) * LSEQ + t0 + tx] = so[r][tx];
}

// ---------------- chunked selective scan ----------------
// pass1: per chunk with h0=0, compute end state + sum(delta)
// grid (CS, D_INNER/16, B), block 256 = 16ch x 16n
__global__ __launch_bounds__(256)
void scan_pass1(const float* __restrict__ A_log)
{
    int c = blockIdx.x, db = blockIdx.y, b = blockIdx.z;
    int n = threadIdx.x & 15, ch = threadIdx.x >> 4;
    int d = db * 16 + ch;

    float Av = -__expf(A_log[d * D_STATE + n]);
    const float* dTp = g_dT + ((size_t)(b * D_INNER) + d) * LSEQ + c * TCH;
    const float* uTp = g_uT + ((size_t)(b * D_INNER) + d) * LSEQ + c * TCH;
    const float* xd  = g_xdbl + ((size_t)(b * LSEQ) + c * TCH) * XDBL;

    float h = 0.f, S = 0.f;
    #pragma unroll 2
    for (int j = 0; j < TCH; j += 4) {
        float4 dv = *reinterpret_cast<const float4*>(dTp + j);
        float4 uv = *reinterpret_cast<const float4*>(uTp + j);
        float dl[4] = {dv.x, dv.y, dv.z, dv.w};
        float uu[4] = {uv.x, uv.y, uv.z, uv.w};
        #pragma unroll
        for (int q = 0; q < 4; q++) {
            float Bv = xd[(size_t)(j + q) * XDBL + DT_RANK + n];
            float a  = __expf(dl[q] * Av);
            h = fmaf(a, h, dl[q] * uu[q] * Bv);
            S += dl[q];
        }
    }
    g_hchk[(((size_t)(b * D_INNER) + d) * CS + c) * D_STATE + n] = h;
    if (n == 0)
        g_schk[((size_t)(b * D_INNER) + d) * CS + c] = S;
}

// combine: sequential prefix over CS chunks per (b,d,n) lane
__global__ void scan_combine(const float* __restrict__ A_log)
{
    int idx = blockIdx.x * blockDim.x + threadIdx.x;  // B*D_INNER*16
    if (idx >= BATCH * D_INNER * D_STATE) return;
    int n = idx & 15;
    int d = (idx >> 4) & (D_INNER - 1);
    int b = idx >> 14;
    float Av = -__expf(A_log[d * D_STATE + n]);
    size_t base = ((size_t)(b * D_INNER) + d) * CS;
    float h0 = 0.f;
    #pragma unroll
    for (int c = 0; c < CS; c++) {
        g_h0[(base + c) * D_STATE + n] = h0;
        float S = g_schk[base + c];
        h0 = g_hchk[(base + c) * D_STATE + n] + __expf(Av * S) * h0;
    }
}

// pass2: recompute with correct h0, emit y = (sum_n h*C + u*D) * silu(z)
__global__ __launch_bounds__(256)
void scan_pass2(const float* __restrict__ A_log, const float* __restrict__ Dv)
{
    int c = blockIdx.x, db = blockIdx.y, b = blockIdx.z;
    int n = threadIdx.x & 15, ch = threadIdx.x >> 4;
    int d = db * 16 + ch;

    float Av = -__expf(A_log[d * D_STATE + n]);
    float Dd = Dv[d];

    const float* dTp = g_dT + ((size_t)(b * D_INNER) + d) * LSEQ + c * TCH;
    const float* uTp = g_uT + ((size_t)(b * D_INNER) + d) * LSEQ + c * TCH;
    const float* xd  = g_xdbl + ((size_t)(b * LSEQ) + c * TCH) * XDBL;
    const float* zP  = g_xz + ((size_t)(b * LSEQ) + c * TCH) * (2 * D_INNER) + D_INNER + d;
    float*       yP  = g_yscan + ((size_t)(b * LSEQ) + c * TCH) * D_INNER + d;

    float h = g_h0[(((size_t)(b * D_INNER) + d) * CS + c) * D_STATE + n];

    #pragma unroll 2
    for (int j = 0; j < TCH; j += 4) {
        float4 dv = *reinterpret_cast<const float4*>(dTp + j);
        float4 uv = *reinterpret_cast<const float4*>(uTp + j);
        float dl[4] = {dv.x, dv.y, dv.z, dv.w};
        float uu[4] = {uv.x, uv.y, uv.z, uv.w};
        #pragma unroll
        for (int q = 0; q < 4; q++) {
            float Bv = xd[(size_t)(j + q) * XDBL + DT_RANK + n];
            float Cv = xd[(size_t)(j + q) * XDBL + DT_RANK + D_STATE + n];
            float a  = __expf(dl[q] * Av);
            h = fmaf(a, h, dl[q] * uu[q] * Bv);
            float p = h * Cv;
            #pragma unroll
            for (int o = 8; o; o >>= 1)
                p += __shfl_xor_sync(0xffffffffu, p, o);
            if (n == 0) {
                float z = zP[(size_t)(j + q) * (2 * D_INNER)];
                float sig = z / (1.f + __expf(-z));
                yP[(size_t)(j + q) * D_INNER] = (p + uu[q] * Dd) * sig;
            }
        }
    }
}

// ---------------- launch ----------------
static float* sym(const void* symbol) {
    void* p = nullptr;
    cudaGetSymbolAddress(&p, symbol);
    return (float*)p;
}

extern "C" void kernel_launch(void* const* d_in, const int* in_sizes, int n_in,
                              void* d_out, int out_size)
{
    const float* x         = (const float*)d_in[0];
    const float* norm_w    = (const float*)d_in[1];
    const float* norm_b    = (const float*)d_in[2];
    const float* in_proj_w = (const float*)d_in[3];
    const float* conv_w    = (const float*)d_in[4];
    const float* conv_b    = (const float*)d_in[5];
    const float* x_proj_w  = (const float*)d_in[6];
    const float* dt_proj_w = (const float*)d_in[7];
    const float* dt_proj_b = (const float*)d_in[8];
    const float* A_log     = (const float*)d_in[9];
    const float* Dv        = (const float*)d_in[10];
    const float* mix_out_w = (const float*)d_in[11];
    const float* match_w   = (const float*)d_in[12];
    const float* match_b   = (const float*)d_in[13];
    const float* geom_w    = (const float*)d_in[14];
    const float* geom_b    = (const float*)d_in[15];
    const float* normm_w   = (const float*)d_in[16];
    const float* normm_b   = (const float*)d_in[17];
    const float* normg_w   = (const float*)d_in[18];
    const float* normg_b   = (const float*)d_in[19];

    float* p_hln   = sym(g_hln);
    float* p_xz    = sym(g_xz);
    float* p_xconv = sym(g_xconv);
    float* p_xdbl  = sym(g_xdbl);
    float* p_dT    = sym(g_dT);
    float* p_yscan = sym(g_yscan);
    float* p_hout  = sym(g_hout);
    float* p_match = sym(g_match);
    float* p_geom  = sym(g_geom);

    float* out_match = (float*)d_out;
    float* out_geom  = (float*)d_out + (size_t)NROWS * DIM;

    // 0. h = layernorm(x)
    layernorm_kernel<<<NROWS, 256>>>(x, norm_w, norm_b, p_hln, DIM);

    // 1. xz = h @ in_proj_w^T   [8192, 2048] K=512
    {
        dim3 grid(2 * D_INNER / 128, NROWS / 128);
        tgemm_kernel<128, EPI_NONE><<<grid, 256>>>(p_hln, DIM, in_proj_w,
                                                   nullptr, nullptr, p_xz,
                                                   NROWS, 2 * D_INNER, DIM);
    }

    // 2. u = silu(conv(xm)) — normal + transposed layouts
    {
        dim3 grid(LSEQ / 32, D_INNER / 32, BATCH);
        conv_silu_T_kernel<<<grid, dim3(32, 8)>>>(conv_w, conv_b);
    }

    // 3. x_dbl = u @ x_proj_w^T   [8192, 64] K=1024
    {
        dim3 grid(XDBL / 64, NROWS / 128);
        tgemm_kernel<64, EPI_NONE><<<grid, 256>>>(p_xconv, D_INNER, x_proj_w,
                                                  nullptr, nullptr, p_xdbl,
                                                  NROWS, XDBL, D_INNER);
    }

    // 4. deltaT = softplus(dt @ dt_proj_w^T + b), stored transposed [b][d][t]
    {
        dim3 grid(D_INNER / 128, NROWS / 128);
        tgemm_kernel<128, EPI_SOFTPL_T><<<grid, 256>>>(p_xdbl, XDBL, dt_proj_w,
                                                       dt_proj_b, nullptr, p_dT,
                                                       NROWS, D_INNER, DT_RANK);
    }

    // 5/6/7. chunked selective scan
    {
        dim3 grid(CS, D_INNER / 16, BATCH);
        scan_pass1<<<grid, 256>>>(A_log);
        scan_combine<<<(BATCH * D_INNER * D_STATE) / 256, 256>>>(A_log);
        scan_pass2<<<grid, 256>>>(A_log, Dv);
    }

    // 8. h_out = y @ mix_out_w^T   [8192, 512] K=1024
    {
        dim3 grid(DIM / 128, NROWS / 128);
        tgemm_kernel<128, EPI_NONE><<<grid, 256>>>(p_yscan, D_INNER, mix_out_w,
                                                   nullptr, nullptr, p_hout,
                                                   NROWS, DIM, D_INNER);
    }

    // 9. match_pre = residual + h_out @ match_w^T + match_b
    {
        dim3 grid(DIM / 128, NROWS / 128);
        tgemm_kernel<128, EPI_RESID><<<grid, 256>>>(p_hout, DIM, match_w,
                                                    match_b, x, p_match,
                                                    NROWS, DIM, DIM);
    }

    // 10. geom_pre = h_out @ geom_w^T + geom_b
    {
        dim3 grid(D_GEOM / 128, NROWS / 128);
        tgemm_kernel<128, EPI_BIAS><<<grid, 256>>>(p_hout, DIM, geom_w,
                                                   geom_b, nullptr, p_geom,
                                                   NROWS, D_GEOM, DIM);
    }

    // 11/12. final layernorms into d_out
    layernorm_kernel<<<NROWS, 256>>>(p_match, normm_w, normm_b, out_match, DIM);
    layernorm_kernel<<<NROWS, 256>>>(p_geom,  normg_w, normg_b, out_geom,  D_GEOM);
}

// round 6
// speedup vs baseline: 3.3466x; 1.0149x over previous
#include <cuda_runtime.h>
#include <cuda_bf16.h>
#include <cstdint>

// ---------------- problem constants ----------------
#define BATCH   4
#define LSEQ    2048
#define NROWS   (BATCH*LSEQ)        // 8192
#define DIM     512
#define D_INNER 1024
#define D_STATE 16
#define D_CONV  4
#define DT_RANK 32
#define XDBL    (DT_RANK + 2*D_STATE)  // 64
#define D_GEOM  256
#define EPSV    1e-5f
#define CS      16                   // scan chunks
#define TCH     (LSEQ/CS)            // 128 steps per chunk

// ---------------- scratch (device globals; no allocation) ----------------
__device__ float g_hln  [NROWS * DIM];
__device__ float g_xz   [NROWS * 2 * D_INNER];
__device__ float g_xconv[NROWS * D_INNER];         // u, [t][d]
__device__ float g_uT   [BATCH * D_INNER * LSEQ];  // u transposed [b][d][t]
__device__ float g_dT   [BATCH * D_INNER * LSEQ];  // delta transposed [b][d][t]
__device__ float g_xdbl [NROWS * XDBL];
__device__ float g_yscan[NROWS * D_INNER];
__device__ float g_hout [NROWS * DIM];
__device__ float g_match[NROWS * DIM];
__device__ float g_geom [NROWS * D_GEOM];
__device__ float g_hchk [BATCH * D_INNER * CS * D_STATE];
__device__ float g_schk [BATCH * D_INNER * CS];
__device__ float g_h0   [BATCH * D_INNER * CS * D_STATE];

// ---------------- layernorm ----------------
__global__ void layernorm_kernel(const float* __restrict__ in,
                                 const float* __restrict__ w,
                                 const float* __restrict__ b,
                                 float* __restrict__ out, int cols)
{
    int row = blockIdx.x;
    const float* p = in + (size_t)row * cols;
    float s = 0.f, sq = 0.f;
    for (int c = threadIdx.x; c < cols; c += blockDim.x) {
        float v = p[c]; s += v; sq += v * v;
    }
    int lane = threadIdx.x & 31, wid = threadIdx.x >> 5;
    #pragma unroll
    for (int o = 16; o; o >>= 1) {
        s  += __shfl_xor_sync(0xffffffffu, s,  o);
        sq += __shfl_xor_sync(0xffffffffu, sq, o);
    }
    __shared__ float shs[8], shq[8];
    if (!lane) { shs[wid] = s; shq[wid] = sq; }
    __syncthreads();
    if (threadIdx.x == 0) {
        float ts = 0.f, tq = 0.f;
        int nw = (blockDim.x + 31) >> 5;
        for (int i = 0; i < nw; i++) { ts += shs[i]; tq += shq[i]; }
        float mu  = ts / cols;
        float var = tq / cols - mu * mu;
        shs[0] = mu;
        shq[0] = rsqrtf(var + EPSV);
    }
    __syncthreads();
    float mu = shs[0], inv = shq[0];
    float* o = out + (size_t)row * cols;
    for (int c = threadIdx.x; c < cols; c += blockDim.x)
        o[c] = (p[c] - mu) * inv * w[c] + b[c];
}

// ---------------- tf32 tensor-core GEMM, cp.async 3-stage pipeline ----------
#define EPI_NONE      0
#define EPI_SOFTPL    1
#define EPI_RESID     2
#define EPI_BIAS      3
#define EPI_SOFTPL_T  4

__device__ __forceinline__ uint32_t f2tf(float f) {
    uint32_t r; asm("cvt.rna.tf32.f32 %0, %1;" : "=r"(r) : "f"(f)); return r;
}

__device__ __forceinline__ void mma_tf32(float* c, const uint32_t* a,
                                         uint32_t b0, uint32_t b1) {
    asm volatile(
        "mma.sync.aligned.m16n8k8.row.col.f32.tf32.tf32.f32 "
        "{%0,%1,%2,%3}, {%4,%5,%6,%7}, {%8,%9}, {%0,%1,%2,%3};"
        : "+f"(c[0]), "+f"(c[1]), "+f"(c[2]), "+f"(c[3])
        : "r"(a[0]), "r"(a[1]), "r"(a[2]), "r"(a[3]), "r"(b0), "r"(b1));
}

__device__ __forceinline__ float softplusf(float v) {
    return (v > 20.f) ? v : log1pf(__expf(v));
}

__device__ __forceinline__ void cp16(uint32_t daddr, const void* gptr) {
    asm volatile("cp.async.cg.shared.global [%0], [%1], 16;" :: "r"(daddr), "l"(gptr));
}
__device__ __forceinline__ void cp_commit() {
    asm volatile("cp.async.commit_group;");
}
template<int N>
__device__ __forceinline__ void cp_wait() {
    asm volatile("cp.async.wait_group %0;" :: "n"(N));
}

// C[M,N] = A[M,K(lda)] * B[N,K]^T. CTA tile 128 x BN, BK=16, 256 thr = 8 warps.
// KSPLIT>1: z slices K, atomicAdd epilogue (C pre-zeroed), bias only on z==0.
template<int BN, int EPI, int KSPLIT>
__global__ __launch_bounds__(256, 2)
void tgemm_kernel(const float* __restrict__ A, int lda,
                  const float* __restrict__ B,
                  const float* __restrict__ bias,
                  const float* __restrict__ resid,
                  float* __restrict__ C,
                  int M, int N, int K)
{
    const int BM = 128, BK = 16, LD = BK + 4, ST = 3;
    const int WN = BN / 16;

    __shared__ float As[ST][BM * LD];
    __shared__ float Bs[ST][BN * LD];

    const int tid  = threadIdx.x;
    const int bm   = blockIdx.y * BM;
    const int bn   = blockIdx.x * BN;
    const int wid  = tid >> 5;
    const int lane = tid & 31;
    const int gid  = lane >> 2;
    const int tig  = lane & 3;
    const int wm   = (wid & 3) * 32;
    const int wn   = (wid >> 2) * (BN / 2);

    const int lrow = tid >> 2;            // 0..63
    const int lkc  = (tid & 3) << 2;      // 0,4,8,12

    const int kchunk = K / KSPLIT;
    const int kbeg   = (KSPLIT > 1) ? blockIdx.z * kchunk : 0;
    const int nslab  = kchunk / BK;

    const float* Ap0 = A + (size_t)(bm + lrow)      * lda + lkc + kbeg;
    const float* Ap1 = A + (size_t)(bm + 64 + lrow) * lda + lkc + kbeg;
    const float* Bp0 = B + (size_t)(bn + lrow)      * K   + lkc + kbeg;
    const float* Bp1 = B + (size_t)(bn + ((BN == 128) ? 64 : 0) + lrow) * K + lkc + kbeg;

    const uint32_t sA = (uint32_t)__cvta_generic_to_shared(As);
    const uint32_t sB = (uint32_t)__cvta_generic_to_shared(Bs);

    auto issue = [&](int s, int slab) {
        int k0 = slab * BK;
        cp16(sA + (uint32_t)((s * BM + lrow)      * LD + lkc) * 4, Ap0 + k0);
        cp16(sA + (uint32_t)((s * BM + 64 + lrow) * LD + lkc) * 4, Ap1 + k0);
        cp16(sB + (uint32_t)((s * BN + lrow)      * LD + lkc) * 4, Bp0 + k0);
        if (BN == 128)
            cp16(sB + (uint32_t)((s * BN + 64 + lrow) * LD + lkc) * 4, Bp1 + k0);
    };

    float acc[2][WN][4];
    #pragma unroll
    for (int i = 0; i < 2; i++)
        #pragma unroll
        for (int f = 0; f < WN; f++)
            #pragma unroll
            for (int j = 0; j < 4; j++)
                acc[i][f][j] = 0.f;

    // prologue: stage ST-1 slabs
    #pragma unroll
    for (int s = 0; s < ST - 1; s++) {
        if (s < nslab) issue(s, s);
        cp_commit();
    }

    for (int i = 0; i < nslab; i++) {
        if (i + ST - 1 < nslab) cp_wait<ST - 2>(); else cp_wait<0>();
        __syncthreads();
        if (i + ST - 1 < nslab) issue((i + ST - 1) % ST, i + ST - 1);
        cp_commit();

        const float* AS = As[i % ST];
        const float* BS = Bs[i % ST];
        #pragma unroll
        for (int kk = 0; kk < BK; kk += 8) {
            uint32_t af[2][4];
            #pragma unroll
            for (int t2 = 0; t2 < 2; t2++) {
                int mb = wm + t2 * 16;
                af[t2][0] = f2tf(AS[(mb + gid)     * LD + kk + tig]);
                af[t2][1] = f2tf(AS[(mb + gid + 8) * LD + kk + tig]);
                af[t2][2] = f2tf(AS[(mb + gid)     * LD + kk + tig + 4]);
                af[t2][3] = f2tf(AS[(mb + gid + 8) * LD + kk + tig + 4]);
            }
            #pragma unroll
            for (int f = 0; f < WN; f++) {
                uint32_t b0 = f2tf(BS[(wn + f * 8 + gid) * LD + kk + tig]);
                uint32_t b1 = f2tf(BS[(wn + f * 8 + gid) * LD + kk + tig + 4]);
                mma_tf32(acc[0][f], af[0], b0, b1);
                mma_tf32(acc[1][f], af[1], b0, b1);
            }
        }
    }

    // ---- epilogue ----
    #pragma unroll
    for (int i = 0; i < 2; i++) {
        #pragma unroll
        for (int rr = 0; rr < 2; rr++) {
            int row = bm + wm + i * 16 + gid + rr * 8;
            float* crow = C + (size_t)row * N;
            const float* rrow = (EPI == EPI_RESID) ? (resid + (size_t)row * N) : nullptr;
            #pragma unroll
            for (int f = 0; f < WN; f++) {
                int col = bn + wn + f * 8 + 2 * tig;
                float v0 = acc[i][f][rr * 2 + 0];
                float v1 = acc[i][f][rr * 2 + 1];
                if (KSPLIT > 1) {
                    if (EPI == EPI_BIAS && blockIdx.z == 0) {
                        v0 += bias[col]; v1 += bias[col + 1];
                    }
                    atomicAdd(&crow[col],     v0);
                    atomicAdd(&crow[col + 1], v1);
                } else if (EPI == EPI_SOFTPL_T) {
                    v0 = softplusf(v0 + bias[col]);
                    v1 = softplusf(v1 + bias[col + 1]);
                    int bb2 = row >> 11, tt = row & (LSEQ - 1);
                    C[((size_t)(bb2 * D_INNER) + col)     * LSEQ + tt] = v0;
                    C[((size_t)(bb2 * D_INNER) + col + 1) * LSEQ + tt] = v1;
                } else {
                    if (EPI == EPI_SOFTPL) {
                        v0 = softplusf(v0 + bias[col]);
                        v1 = softplusf(v1 + bias[col + 1]);
                    } else if (EPI == EPI_RESID) {
                        v0 += bias[col]     + rrow[col];
                        v1 += bias[col + 1] + rrow[col + 1];
                    } else if (EPI == EPI_BIAS) {
                        v0 += bias[col]; v1 += bias[col + 1];
                    }
                    *reinterpret_cast<float2*>(&crow[col]) = make_float2(v0, v1);
                }
            }
        }
    }
}

// ---------------- depthwise causal conv + silu, dual-layout output ----------------
__global__ __launch_bounds__(256)
void conv_silu_T_kernel(const float* __restrict__ conv_w,
                        const float* __restrict__ conv_b)
{
    __shared__ float sx[35][33];
    __shared__ float so[32][33];
    int t0 = blockIdx.x * 32, d0 = blockIdx.y * 32, b = blockIdx.z;
    int tx = threadIdx.x, ty = threadIdx.y;

    for (int r = ty; r < 35; r += 8) {
        int t = t0 - 3 + r;
        float v = (t >= 0) ? g_xz[((size_t)(b * LSEQ) + t) * (2 * D_INNER) + d0 + tx] : 0.f;
        sx[r][tx] = v;
    }
    __syncthreads();

    int d = d0 + tx;
    float w0 = conv_w[d * 4 + 0], w1 = conv_w[d * 4 + 1];
    float w2 = conv_w[d * 4 + 2], w3 = conv_w[d * 4 + 3];
    float bb = conv_b[d];
    for (int r = ty; r < 32; r += 8) {
        float acc = bb;
        acc = fmaf(w0, sx[r][tx],     acc);
        acc = fmaf(w1, sx[r + 1][tx], acc);
        acc = fmaf(w2, sx[r + 2][tx], acc);
        acc = fmaf(w3, sx[r + 3][tx], acc);
        float sv = acc / (1.f + __expf(-acc));
        g_xconv[((size_t)(b * LSEQ) + t0 + r) * D_INNER + d] = sv;
        so[tx][r] = sv;
    }
    __syncthreads();

    for (int r = ty; r < 32; r += 8)
        g_uT[((size_t)(b * D_INNER) + d0 + r) * LSEQ + t0 + tx] = so[r][tx];
}

// ---------------- chunked selective scan ----------------
__global__ __launch_bounds__(256)
void scan_pass1(const float* __restrict__ A_log)
{
    int c = blockIdx.x, db = blockIdx.y, b = blockIdx.z;
    int n = threadIdx.x & 15, ch = threadIdx.x >> 4;
    int d = db * 16 + ch;

    float Av = -__expf(A_log[d * D_STATE + n]);
    const float* dTp = g_dT + ((size_t)(b * D_INNER) + d) * LSEQ + c * TCH;
    const float* uTp = g_uT + ((size_t)(b * D_INNER) + d) * LSEQ + c * TCH;
    const float* xd  = g_xdbl + ((size_t)(b * LSEQ) + c * TCH) * XDBL;

    float h = 0.f, S = 0.f;
    #pragma unroll 2
    for (int j = 0; j < TCH; j += 4) {
        float4 dv = *reinterpret_cast<const float4*>(dTp + j);
        float4 uv = *reinterpret_cast<const float4*>(uTp + j);
        float dl[4] = {dv.x, dv.y, dv.z, dv.w};
        float uu[4] = {uv.x, uv.y, uv.z, uv.w};
        #pragma unroll
        for (int q = 0; q < 4; q++) {
            float Bv = xd[(size_t)(j + q) * XDBL + DT_RANK + n];
            float a  = __expf(dl[q] * Av);
            h = fmaf(a, h, dl[q] * uu[q] * Bv);
            S += dl[q];
        }
    }
    g_hchk[(((size_t)(b * D_INNER) + d) * CS + c) * D_STATE + n] = h;
    if (n == 0)
        g_schk[((size_t)(b * D_INNER) + d) * CS + c] = S;
}

__global__ void scan_combine(const float* __restrict__ A_log)
{
    int idx = blockIdx.x * blockDim.x + threadIdx.x;
    if (idx >= BATCH * D_INNER * D_STATE) return;
    int n = idx & 15;
    int d = (idx >> 4) & (D_INNER - 1);
    int b = idx >> 14;
    float Av = -__expf(A_log[d * D_STATE + n]);
    size_t base = ((size_t)(b * D_INNER) + d) * CS;
    float h0 = 0.f;
    #pragma unroll
    for (int c = 0; c < CS; c++) {
        g_h0[(base + c) * D_STATE + n] = h0;
        float S = g_schk[base + c];
        h0 = g_hchk[(base + c) * D_STATE + n] + __expf(Av * S) * h0;
    }
}

__global__ __launch_bounds__(256)
void scan_pass2(const float* __restrict__ A_log, const float* __restrict__ Dv)
{
    int c = blockIdx.x, db = blockIdx.y, b = blockIdx.z;
    int n = threadIdx.x & 15, ch = threadIdx.x >> 4;
    int d = db * 16 + ch;

    float Av = -__expf(A_log[d * D_STATE + n]);
    float Dd = Dv[d];

    const float* dTp = g_dT + ((size_t)(b * D_INNER) + d) * LSEQ + c * TCH;
    const float* uTp = g_uT + ((size_t)(b * D_INNER) + d) * LSEQ + c * TCH;
    const float* xd  = g_xdbl + ((size_t)(b * LSEQ) + c * TCH) * XDBL;
    const float* zP  = g_xz + ((size_t)(b * LSEQ) + c * TCH) * (2 * D_INNER) + D_INNER + d;
    float*       yP  = g_yscan + ((size_t)(b * LSEQ) + c * TCH) * D_INNER + d;

    float h = g_h0[(((size_t)(b * D_INNER) + d) * CS + c) * D_STATE + n];

    #pragma unroll 2
    for (int j = 0; j < TCH; j += 4) {
        float4 dv = *reinterpret_cast<const float4*>(dTp + j);
        float4 uv = *reinterpret_cast<const float4*>(uTp + j);
        float dl[4] = {dv.x, dv.y, dv.z, dv.w};
        float uu[4] = {uv.x, uv.y, uv.z, uv.w};
        #pragma unroll
        for (int q = 0; q < 4; q++) {
            float Bv = xd[(size_t)(j + q) * XDBL + DT_RANK + n];
            float Cv = xd[(size_t)(j + q) * XDBL + DT_RANK + D_STATE + n];
            float a  = __expf(dl[q] * Av);
            h = fmaf(a, h, dl[q] * uu[q] * Bv);
            float p = h * Cv;
            #pragma unroll
            for (int o = 8; o; o >>= 1)
                p += __shfl_xor_sync(0xffffffffu, p, o);
            if (n == 0) {
                float z = zP[(size_t)(j + q) * (2 * D_INNER)];
                float sig = z / (1.f + __expf(-z));
                yP[(size_t)(j + q) * D_INNER] = (p + uu[q] * Dd) * sig;
            }
        }
    }
}

// ---------------- launch ----------------
static float* sym(const void* symbol) {
    void* p = nullptr;
    cudaGetSymbolAddress(&p, symbol);
    return (float*)p;
}

extern "C" void kernel_launch(void* const* d_in, const int* in_sizes, int n_in,
                              void* d_out, int out_size)
{
    const float* x         = (const float*)d_in[0];
    const float* norm_w    = (const float*)d_in[1];
    const float* norm_b    = (const float*)d_in[2];
    const float* in_proj_w = (const float*)d_in[3];
    const float* conv_w    = (const float*)d_in[4];
    const float* conv_b    = (const float*)d_in[5];
    const float* x_proj_w  = (const float*)d_in[6];
    const float* dt_proj_w = (const float*)d_in[7];
    const float* dt_proj_b = (const float*)d_in[8];
    const float* A_log     = (const float*)d_in[9];
    const float* Dv        = (const float*)d_in[10];
    const float* mix_out_w = (const float*)d_in[11];
    const float* match_w   = (const float*)d_in[12];
    const float* match_b   = (const float*)d_in[13];
    const float* geom_w    = (const float*)d_in[14];
    const float* geom_b    = (const float*)d_in[15];
    const float* normm_w   = (const float*)d_in[16];
    const float* normm_b   = (const float*)d_in[17];
    const float* normg_w   = (const float*)d_in[18];
    const float* normg_b   = (const float*)d_in[19];

    float* p_hln   = sym(g_hln);
    float* p_xz    = sym(g_xz);
    float* p_xconv = sym(g_xconv);
    float* p_xdbl  = sym(g_xdbl);
    float* p_dT    = sym(g_dT);
    float* p_yscan = sym(g_yscan);
    float* p_hout  = sym(g_hout);
    float* p_match = sym(g_match);
    float* p_geom  = sym(g_geom);

    float* out_match = (float*)d_out;
    float* out_geom  = (float*)d_out + (size_t)NROWS * DIM;

    // 0. h = layernorm(x)
    layernorm_kernel<<<NROWS, 256>>>(x, norm_w, norm_b, p_hln, DIM);

    // 1. xz = h @ in_proj_w^T   [8192, 2048] K=512  (1024 CTAs)
    {
        dim3 grid(2 * D_INNER / 128, NROWS / 128);
        tgemm_kernel<128, EPI_NONE, 1><<<grid, 256>>>(p_hln, DIM, in_proj_w,
                                                      nullptr, nullptr, p_xz,
                                                      NROWS, 2 * D_INNER, DIM);
    }

    // 2. u = silu(conv(xm)) — normal + transposed layouts
    {
        dim3 grid(LSEQ / 32, D_INNER / 32, BATCH);
        conv_silu_T_kernel<<<grid, dim3(32, 8)>>>(conv_w, conv_b);
    }

    // 3. x_dbl = u @ x_proj_w^T [8192,64] K=1024, split-K=4 (256 CTAs)
    cudaMemsetAsync(p_xdbl, 0, (size_t)NROWS * XDBL * sizeof(float));
    {
        dim3 grid(XDBL / 64, NROWS / 128, 4);
        tgemm_kernel<64, EPI_NONE, 4><<<grid, 256>>>(p_xconv, D_INNER, x_proj_w,
                                                     nullptr, nullptr, p_xdbl,
                                                     NROWS, XDBL, D_INNER);
    }

    // 4. deltaT = softplus(dt @ dt_proj_w^T + b), stored transposed (512 CTAs)
    {
        dim3 grid(D_INNER / 128, NROWS / 128);
        tgemm_kernel<128, EPI_SOFTPL_T, 1><<<grid, 256>>>(p_xdbl, XDBL, dt_proj_w,
                                                          dt_proj_b, nullptr, p_dT,
                                                          NROWS, D_INNER, DT_RANK);
    }

    // 5/6/7. chunked selective scan
    {
        dim3 grid(CS, D_INNER / 16, BATCH);
        scan_pass1<<<grid, 256>>>(A_log);
        scan_combine<<<(BATCH * D_INNER * D_STATE) / 256, 256>>>(A_log);
        scan_pass2<<<grid, 256>>>(A_log, Dv);
    }

    // 8. h_out = y @ mix_out_w^T [8192,512] K=1024, split-K=2 (512 CTAs)
    cudaMemsetAsync(p_hout, 0, (size_t)NROWS * DIM * sizeof(float));
    {
        dim3 grid(DIM / 128, NROWS / 128, 2);
        tgemm_kernel<128, EPI_NONE, 2><<<grid, 256>>>(p_yscan, D_INNER, mix_out_w,
                                                      nullptr, nullptr, p_hout,
                                                      NROWS, DIM, D_INNER);
    }

    // 9. match_pre = residual + h_out @ match_w^T + match_b (256 CTAs)
    {
        dim3 grid(DIM / 128, NROWS / 128);
        tgemm_kernel<128, EPI_RESID, 1><<<grid, 256>>>(p_hout, DIM, match_w,
                                                       match_b, x, p_match,
                                                       NROWS, DIM, DIM);
    }

    // 10. geom_pre = h_out @ geom_w^T + geom_b [8192,256] K=512, split-K=2 (256 CTAs)
    cudaMemsetAsync(p_geom, 0, (size_t)NROWS * D_GEOM * sizeof(float));
    {
        dim3 grid(D_GEOM / 128, NROWS / 128, 2);
        tgemm_kernel<128, EPI_BIAS, 2><<<grid, 256>>>(p_hout, DIM, geom_w,
                                                      geom_b, nullptr, p_geom,
                                                      NROWS, D_GEOM, DIM);
    }

    // 11/12. final layernorms into d_out
    layernorm_kernel<<<NROWS, 256>>>(p_match, normm_w, normm_b, out_match, DIM);
    layernorm_kernel<<<NROWS, 256>>>(p_geom,  normg_w, normg_b, out_geom,  D_GEOM);
}

// round 7
// speedup vs baseline: 3.4567x; 1.0329x over previous
#include <cuda_runtime.h>
#include <cuda_bf16.h>
#include <cstdint>

// ---------------- problem constants ----------------
#define BATCH   4
#define LSEQ    2048
#define NROWS   (BATCH*LSEQ)        // 8192
#define DIM     512
#define D_INNER 1024
#define D_STATE 16
#define D_CONV  4
#define DT_RANK 32
#define XDBL    (DT_RANK + 2*D_STATE)  // 64
#define D_GEOM  256
#define EPSV    1e-5f
#define CS      16                   // scan chunks
#define TCH     (LSEQ/CS)            // 128 steps per chunk

// weight copy sizes
#define W_IP (2*D_INNER*DIM)     // 1048576
#define W_XP (XDBL*D_INNER)      // 65536
#define W_DT (D_INNER*DT_RANK)   // 32768
#define W_MO (DIM*D_INNER)       // 524288
#define W_MA (DIM*DIM)           // 262144
#define W_GE (D_GEOM*DIM)        // 131072

// ---------------- scratch (device globals; no allocation) ----------------
__device__ float g_hln  [NROWS * DIM];
__device__ float g_xz   [NROWS * 2 * D_INNER];
__device__ float g_xconv[NROWS * D_INNER];         // u, [t][d]
__device__ float g_uT   [BATCH * D_INNER * LSEQ];  // u transposed [b][d][t]
__device__ float g_dT   [BATCH * D_INNER * LSEQ];  // delta transposed [b][d][t]
__device__ float g_xdbl [NROWS * XDBL];
__device__ float g_yscan[NROWS * D_INNER];
__device__ float g_hout [NROWS * DIM];
__device__ float g_match[NROWS * DIM];
__device__ float g_geom [NROWS * D_GEOM];
__device__ float g_hchk [BATCH * D_INNER * CS * D_STATE];
__device__ float g_schk [BATCH * D_INNER * CS];
__device__ float g_h0   [BATCH * D_INNER * CS * D_STATE];
// pre-rounded (tf32) weight copies
__device__ float g_wip[W_IP];
__device__ float g_wxp[W_XP];
__device__ float g_wdt[W_DT];
__device__ float g_wmo[W_MO];
__device__ float g_wma[W_MA];
__device__ float g_wge[W_GE];

__device__ __forceinline__ uint32_t f2tf(float f) {
    uint32_t r; asm("cvt.rna.tf32.f32 %0, %1;" : "=r"(r) : "f"(f)); return r;
}
__device__ __forceinline__ float f2tf_f(float f) {
    return __uint_as_float(f2tf(f));
}

// ---------------- weight pre-rounding ----------------
__global__ void round_weights_kernel(const float* __restrict__ ip,
                                     const float* __restrict__ xp,
                                     const float* __restrict__ dt,
                                     const float* __restrict__ mo,
                                     const float* __restrict__ ma,
                                     const float* __restrict__ ge)
{
    int i = blockIdx.x * blockDim.x + threadIdx.x;
    int total = W_IP + W_XP + W_DT + W_MO + W_MA + W_GE;
    if (i >= total) return;
    if (i < W_IP) { g_wip[i] = f2tf_f(ip[i]); return; }
    i -= W_IP;
    if (i < W_XP) { g_wxp[i] = f2tf_f(xp[i]); return; }
    i -= W_XP;
    if (i < W_DT) { g_wdt[i] = f2tf_f(dt[i]); return; }
    i -= W_DT;
    if (i < W_MO) { g_wmo[i] = f2tf_f(mo[i]); return; }
    i -= W_MO;
    if (i < W_MA) { g_wma[i] = f2tf_f(ma[i]); return; }
    i -= W_MA;
    g_wge[i] = f2tf_f(ge[i]);
}

// round a buffer in place (for h_out after split-K atomics)
__global__ void round_buf_kernel(float* __restrict__ p, int n4)
{
    int i = blockIdx.x * blockDim.x + threadIdx.x;
    if (i >= n4) return;
    float4 v = reinterpret_cast<float4*>(p)[i];
    v.x = f2tf_f(v.x); v.y = f2tf_f(v.y);
    v.z = f2tf_f(v.z); v.w = f2tf_f(v.w);
    reinterpret_cast<float4*>(p)[i] = v;
}

// ---------------- layernorm ----------------
template<bool RND>
__global__ void layernorm_kernel(const float* __restrict__ in,
                                 const float* __restrict__ w,
                                 const float* __restrict__ b,
                                 float* __restrict__ out, int cols)
{
    int row = blockIdx.x;
    const float* p = in + (size_t)row * cols;
    float s = 0.f, sq = 0.f;
    for (int c = threadIdx.x; c < cols; c += blockDim.x) {
        float v = p[c]; s += v; sq += v * v;
    }
    int lane = threadIdx.x & 31, wid = threadIdx.x >> 5;
    #pragma unroll
    for (int o = 16; o; o >>= 1) {
        s  += __shfl_xor_sync(0xffffffffu, s,  o);
        sq += __shfl_xor_sync(0xffffffffu, sq, o);
    }
    __shared__ float shs[8], shq[8];
    if (!lane) { shs[wid] = s; shq[wid] = sq; }
    __syncthreads();
    if (threadIdx.x == 0) {
        float ts = 0.f, tq = 0.f;
        int nw = (blockDim.x + 31) >> 5;
        for (int i = 0; i < nw; i++) { ts += shs[i]; tq += shq[i]; }
        float mu  = ts / cols;
        float var = tq / cols - mu * mu;
        shs[0] = mu;
        shq[0] = rsqrtf(var + EPSV);
    }
    __syncthreads();
    float mu = shs[0], inv = shq[0];
    float* o = out + (size_t)row * cols;
    for (int c = threadIdx.x; c < cols; c += blockDim.x) {
        float v = (p[c] - mu) * inv * w[c] + b[c];
        o[c] = RND ? f2tf_f(v) : v;
    }
}

// ---------------- tf32 tensor-core GEMM, cp.async 3-stage pipeline ----------
#define EPI_NONE      0
#define EPI_SOFTPL    1
#define EPI_RESID     2
#define EPI_BIAS      3
#define EPI_SOFTPL_T  4

__device__ __forceinline__ void mma_tf32(float* c, const uint32_t* a,
                                         uint32_t b0, uint32_t b1) {
    asm volatile(
        "mma.sync.aligned.m16n8k8.row.col.f32.tf32.tf32.f32 "
        "{%0,%1,%2,%3}, {%4,%5,%6,%7}, {%8,%9}, {%0,%1,%2,%3};"
        : "+f"(c[0]), "+f"(c[1]), "+f"(c[2]), "+f"(c[3])
        : "r"(a[0]), "r"(a[1]), "r"(a[2]), "r"(a[3]), "r"(b0), "r"(b1));
}

__device__ __forceinline__ float softplusf(float v) {
    return (v > 20.f) ? v : log1pf(__expf(v));
}

__device__ __forceinline__ void cp16(uint32_t daddr, const void* gptr) {
    asm volatile("cp.async.cg.shared.global [%0], [%1], 16;" :: "r"(daddr), "l"(gptr));
}
__device__ __forceinline__ void cp_commit() {
    asm volatile("cp.async.commit_group;");
}
template<int N>
__device__ __forceinline__ void cp_wait() {
    asm volatile("cp.async.wait_group %0;" :: "n"(N));
}

// C[M,N] = A[M,K(lda)] * B[N,K]^T. CTA tile 128 x BN, BK=16, 256 thr = 8 warps.
// B must be pre-rounded to tf32. A pre-rounded unless CVTA.
// KSPLIT>1: z slices K, atomicAdd epilogue (C pre-zeroed), bias only on z==0.
template<int BN, int EPI, int KSPLIT, bool CVTA>
__global__ __launch_bounds__(256, 2)
void tgemm_kernel(const float* __restrict__ A, int lda,
                  const float* __restrict__ B,
                  const float* __restrict__ bias,
                  const float* __restrict__ resid,
                  float* __restrict__ C,
                  int M, int N, int K)
{
    const int BM = 128, BK = 16, LD = BK + 4, ST = 3;
    const int WN = BN / 16;

    __shared__ float As[ST][BM * LD];
    __shared__ float Bs[ST][BN * LD];

    const int tid  = threadIdx.x;
    const int bm   = blockIdx.y * BM;
    const int bn   = blockIdx.x * BN;
    const int wid  = tid >> 5;
    const int lane = tid & 31;
    const int gid  = lane >> 2;
    const int tig  = lane & 3;
    const int wm   = (wid & 3) * 32;
    const int wn   = (wid >> 2) * (BN / 2);

    const int lrow = tid >> 2;            // 0..63
    const int lkc  = (tid & 3) << 2;      // 0,4,8,12

    const int kchunk = K / KSPLIT;
    const int kbeg   = (KSPLIT > 1) ? blockIdx.z * kchunk : 0;
    const int nslab  = kchunk / BK;

    const float* Ap0 = A + (size_t)(bm + lrow)      * lda + lkc + kbeg;
    const float* Ap1 = A + (size_t)(bm + 64 + lrow) * lda + lkc + kbeg;
    const float* Bp0 = B + (size_t)(bn + lrow)      * K   + lkc + kbeg;
    const float* Bp1 = B + (size_t)(bn + ((BN == 128) ? 64 : 0) + lrow) * K + lkc + kbeg;

    const uint32_t sA = (uint32_t)__cvta_generic_to_shared(As);
    const uint32_t sB = (uint32_t)__cvta_generic_to_shared(Bs);

    auto issue = [&](int s, int slab) {
        int k0 = slab * BK;
        cp16(sA + (uint32_t)((s * BM + lrow)      * LD + lkc) * 4, Ap0 + k0);
        cp16(sA + (uint32_t)((s * BM + 64 + lrow) * LD + lkc) * 4, Ap1 + k0);
        cp16(sB + (uint32_t)((s * BN + lrow)      * LD + lkc) * 4, Bp0 + k0);
        if (BN == 128)
            cp16(sB + (uint32_t)((s * BN + 64 + lrow) * LD + lkc) * 4, Bp1 + k0);
    };

    float acc[2][WN][4];
    #pragma unroll
    for (int i = 0; i < 2; i++)
        #pragma unroll
        for (int f = 0; f < WN; f++)
            #pragma unroll
            for (int j = 0; j < 4; j++)
                acc[i][f][j] = 0.f;

    #pragma unroll
    for (int s = 0; s < ST - 1; s++) {
        if (s < nslab) issue(s, s);
        cp_commit();
    }

    for (int i = 0; i < nslab; i++) {
        if (i + ST - 1 < nslab) cp_wait<ST - 2>(); else cp_wait<0>();
        __syncthreads();
        if (i + ST - 1 < nslab) issue((i + ST - 1) % ST, i + ST - 1);
        cp_commit();

        const float* AS = As[i % ST];
        const uint32_t* ASu = reinterpret_cast<const uint32_t*>(AS);
        const uint32_t* BSu = reinterpret_cast<const uint32_t*>(Bs[i % ST]);
        #pragma unroll
        for (int kk = 0; kk < BK; kk += 8) {
            uint32_t af[2][4];
            #pragma unroll
            for (int t2 = 0; t2 < 2; t2++) {
                int mb = wm + t2 * 16;
                if (CVTA) {
                    af[t2][0] = f2tf(AS[(mb + gid)     * LD + kk + tig]);
                    af[t2][1] = f2tf(AS[(mb + gid + 8) * LD + kk + tig]);
                    af[t2][2] = f2tf(AS[(mb + gid)     * LD + kk + tig + 4]);
                    af[t2][3] = f2tf(AS[(mb + gid + 8) * LD + kk + tig + 4]);
                } else {
                    af[t2][0] = ASu[(mb + gid)     * LD + kk + tig];
                    af[t2][1] = ASu[(mb + gid + 8) * LD + kk + tig];
                    af[t2][2] = ASu[(mb + gid)     * LD + kk + tig + 4];
                    af[t2][3] = ASu[(mb + gid + 8) * LD + kk + tig + 4];
                }
            }
            #pragma unroll
            for (int f = 0; f < WN; f++) {
                uint32_t b0 = BSu[(wn + f * 8 + gid) * LD + kk + tig];
                uint32_t b1 = BSu[(wn + f * 8 + gid) * LD + kk + tig + 4];
                mma_tf32(acc[0][f], af[0], b0, b1);
                mma_tf32(acc[1][f], af[1], b0, b1);
            }
        }
    }

    // ---- epilogue ----
    #pragma unroll
    for (int i = 0; i < 2; i++) {
        #pragma unroll
        for (int rr = 0; rr < 2; rr++) {
            int row = bm + wm + i * 16 + gid + rr * 8;
            float* crow = C + (size_t)row * N;
            const float* rrow = (EPI == EPI_RESID) ? (resid + (size_t)row * N) : nullptr;
            #pragma unroll
            for (int f = 0; f < WN; f++) {
                int col = bn + wn + f * 8 + 2 * tig;
                float v0 = acc[i][f][rr * 2 + 0];
                float v1 = acc[i][f][rr * 2 + 1];
                if (KSPLIT > 1) {
                    if (EPI == EPI_BIAS && blockIdx.z == 0) {
                        v0 += bias[col]; v1 += bias[col + 1];
                    }
                    atomicAdd(&crow[col],     v0);
                    atomicAdd(&crow[col + 1], v1);
                } else if (EPI == EPI_SOFTPL_T) {
                    v0 = softplusf(v0 + bias[col]);
                    v1 = softplusf(v1 + bias[col + 1]);
                    int bb2 = row >> 11, tt = row & (LSEQ - 1);
                    C[((size_t)(bb2 * D_INNER) + col)     * LSEQ + tt] = v0;
                    C[((size_t)(bb2 * D_INNER) + col + 1) * LSEQ + tt] = v1;
                } else {
                    if (EPI == EPI_SOFTPL) {
                        v0 = softplusf(v0 + bias[col]);
                        v1 = softplusf(v1 + bias[col + 1]);
                    } else if (EPI == EPI_RESID) {
                        v0 += bias[col]     + rrow[col];
                        v1 += bias[col + 1] + rrow[col + 1];
                    } else if (EPI == EPI_BIAS) {
                        v0 += bias[col]; v1 += bias[col + 1];
                    }
                    *reinterpret_cast<float2*>(&crow[col]) = make_float2(v0, v1);
                }
            }
        }
    }
}

// ---------------- depthwise causal conv + silu, dual-layout output ----------------
__global__ __launch_bounds__(256)
void conv_silu_T_kernel(const float* __restrict__ conv_w,
                        const float* __restrict__ conv_b)
{
    __shared__ float sx[35][33];
    __shared__ float so[32][33];
    int t0 = blockIdx.x * 32, d0 = blockIdx.y * 32, b = blockIdx.z;
    int tx = threadIdx.x, ty = threadIdx.y;

    for (int r = ty; r < 35; r += 8) {
        int t = t0 - 3 + r;
        float v = (t >= 0) ? g_xz[((size_t)(b * LSEQ) + t) * (2 * D_INNER) + d0 + tx] : 0.f;
        sx[r][tx] = v;
    }
    __syncthreads();

    int d = d0 + tx;
    float w0 = conv_w[d * 4 + 0], w1 = conv_w[d * 4 + 1];
    float w2 = conv_w[d * 4 + 2], w3 = conv_w[d * 4 + 3];
    float bb = conv_b[d];
    for (int r = ty; r < 32; r += 8) {
        float acc = bb;
        acc = fmaf(w0, sx[r][tx],     acc);
        acc = fmaf(w1, sx[r + 1][tx], acc);
        acc = fmaf(w2, sx[r + 2][tx], acc);
        acc = fmaf(w3, sx[r + 3][tx], acc);
        float sv = acc / (1.f + __expf(-acc));
        g_xconv[((size_t)(b * LSEQ) + t0 + r) * D_INNER + d] = sv;
        so[tx][r] = sv;
    }
    __syncthreads();

    for (int r = ty; r < 32; r += 8)
        g_uT[((size_t)(b * D_INNER) + d0 + r) * LSEQ + t0 + tx] = so[r][tx];
}

// ---------------- chunked selective scan ----------------
__global__ __launch_bounds__(256)
void scan_pass1(const float* __restrict__ A_log)
{
    int c = blockIdx.x, db = blockIdx.y, b = blockIdx.z;
    int n = threadIdx.x & 15, ch = threadIdx.x >> 4;
    int d = db * 16 + ch;

    float Av = -__expf(A_log[d * D_STATE + n]);
    const float* dTp = g_dT + ((size_t)(b * D_INNER) + d) * LSEQ + c * TCH;
    const float* uTp = g_uT + ((size_t)(b * D_INNER) + d) * LSEQ + c * TCH;
    const float* xd  = g_xdbl + ((size_t)(b * LSEQ) + c * TCH) * XDBL;

    float h = 0.f, S = 0.f;
    #pragma unroll 2
    for (int j = 0; j < TCH; j += 4) {
        float4 dv = *reinterpret_cast<const float4*>(dTp + j);
        float4 uv = *reinterpret_cast<const float4*>(uTp + j);
        float dl[4] = {dv.x, dv.y, dv.z, dv.w};
        float uu[4] = {uv.x, uv.y, uv.z, uv.w};
        #pragma unroll
        for (int q = 0; q < 4; q++) {
            float Bv = xd[(size_t)(j + q) * XDBL + DT_RANK + n];
            float a  = __expf(dl[q] * Av);
            h = fmaf(a, h, dl[q] * uu[q] * Bv);
            S += dl[q];
        }
    }
    g_hchk[(((size_t)(b * D_INNER) + d) * CS + c) * D_STATE + n] = h;
    if (n == 0)
        g_schk[((size_t)(b * D_INNER) + d) * CS + c] = S;
}

__global__ void scan_combine(const float* __restrict__ A_log)
{
    int idx = blockIdx.x * blockDim.x + threadIdx.x;
    if (idx >= BATCH * D_INNER * D_STATE) return;
    int n = idx & 15;
    int d = (idx >> 4) & (D_INNER - 1);
    int b = idx >> 14;
    float Av = -__expf(A_log[d * D_STATE + n]);
    size_t base = ((size_t)(b * D_INNER) + d) * CS;
    float h0 = 0.f;
    #pragma unroll
    for (int c = 0; c < CS; c++) {
        g_h0[(base + c) * D_STATE + n] = h0;
        float S = g_schk[base + c];
        h0 = g_hchk[(base + c) * D_STATE + n] + __expf(Av * S) * h0;
    }
}

__global__ __launch_bounds__(256)
void scan_pass2(const float* __restrict__ A_log, const float* __restrict__ Dv)
{
    int c = blockIdx.x, db = blockIdx.y, b = blockIdx.z;
    int n = threadIdx.x & 15, ch = threadIdx.x >> 4;
    int d = db * 16 + ch;

    float Av = -__expf(A_log[d * D_STATE + n]);
    float Dd = Dv[d];

    const float* dTp = g_dT + ((size_t)(b * D_INNER) + d) * LSEQ + c * TCH;
    const float* uTp = g_uT + ((size_t)(b * D_INNER) + d) * LSEQ + c * TCH;
    const float* xd  = g_xdbl + ((size_t)(b * LSEQ) + c * TCH) * XDBL;
    const float* zP  = g_xz + ((size_t)(b * LSEQ) + c * TCH) * (2 * D_INNER) + D_INNER + d;
    float*       yP  = g_yscan + ((size_t)(b * LSEQ) + c * TCH) * D_INNER + d;

    float h = g_h0[(((size_t)(b * D_INNER) + d) * CS + c) * D_STATE + n];

    #pragma unroll 2
    for (int j = 0; j < TCH; j += 4) {
        float4 dv = *reinterpret_cast<const float4*>(dTp + j);
        float4 uv = *reinterpret_cast<const float4*>(uTp + j);
        float dl[4] = {dv.x, dv.y, dv.z, dv.w};
        float uu[4] = {uv.x, uv.y, uv.z, uv.w};
        #pragma unroll
        for (int q = 0; q < 4; q++) {
            float Bv = xd[(size_t)(j + q) * XDBL + DT_RANK + n];
            float Cv = xd[(size_t)(j + q) * XDBL + DT_RANK + D_STATE + n];
            float a  = __expf(dl[q] * Av);
            h = fmaf(a, h, dl[q] * uu[q] * Bv);
            float p = h * Cv;
            #pragma unroll
            for (int o = 8; o; o >>= 1)
                p += __shfl_xor_sync(0xffffffffu, p, o);
            if (n == 0) {
                float z = zP[(size_t)(j + q) * (2 * D_INNER)];
                float sig = z / (1.f + __expf(-z));
                // rounded to tf32: feeds only mix_out GEMM (A side)
                yP[(size_t)(j + q) * D_INNER] = f2tf_f((p + uu[q] * Dd) * sig);
            }
        }
    }
}

// ---------------- launch ----------------
static float* sym(const void* symbol) {
    void* p = nullptr;
    cudaGetSymbolAddress(&p, symbol);
    return (float*)p;
}

extern "C" void kernel_launch(void* const* d_in, const int* in_sizes, int n_in,
                              void* d_out, int out_size)
{
    const float* x         = (const float*)d_in[0];
    const float* norm_w    = (const float*)d_in[1];
    const float* norm_b    = (const float*)d_in[2];
    const float* in_proj_w = (const float*)d_in[3];
    const float* conv_w    = (const float*)d_in[4];
    const float* conv_b    = (const float*)d_in[5];
    const float* x_proj_w  = (const float*)d_in[6];
    const float* dt_proj_w = (const float*)d_in[7];
    const float* dt_proj_b = (const float*)d_in[8];
    const float* A_log     = (const float*)d_in[9];
    const float* Dv        = (const float*)d_in[10];
    const float* mix_out_w = (const float*)d_in[11];
    const float* match_w   = (const float*)d_in[12];
    const float* match_b   = (const float*)d_in[13];
    const float* geom_w    = (const float*)d_in[14];
    const float* geom_b    = (const float*)d_in[15];
    const float* normm_w   = (const float*)d_in[16];
    const float* normm_b   = (const float*)d_in[17];
    const float* normg_w   = (const float*)d_in[18];
    const float* normg_b   = (const float*)d_in[19];

    float* p_hln   = sym(g_hln);
    float* p_xz    = sym(g_xz);
    float* p_xconv = sym(g_xconv);
    float* p_xdbl  = sym(g_xdbl);
    float* p_dT    = sym(g_dT);
    float* p_yscan = sym(g_yscan);
    float* p_hout  = sym(g_hout);
    float* p_match = sym(g_match);
    float* p_geom  = sym(g_geom);
    float* p_wip   = sym(g_wip);
    float* p_wxp   = sym(g_wxp);
    float* p_wdt   = sym(g_wdt);
    float* p_wmo   = sym(g_wmo);
    float* p_wma   = sym(g_wma);
    float* p_wge   = sym(g_wge);

    float* out_match = (float*)d_out;
    float* out_geom  = (float*)d_out + (size_t)NROWS * DIM;

    // W. pre-round all weights to tf32
    {
        int total = W_IP + W_XP + W_DT + W_MO + W_MA + W_GE;
        round_weights_kernel<<<(total + 255) / 256, 256>>>(in_proj_w, x_proj_w,
                                                           dt_proj_w, mix_out_w,
                                                           match_w, geom_w);
    }

    // 0. h = layernorm(x), rounded (feeds only in_proj GEMM)
    layernorm_kernel<true><<<NROWS, 256>>>(x, norm_w, norm_b, p_hln, DIM);

    // 1. xz = h @ in_proj_w^T   [8192, 2048] K=512  (1024 CTAs)
    {
        dim3 grid(2 * D_INNER / 128, NROWS / 128);
        tgemm_kernel<128, EPI_NONE, 1, false><<<grid, 256>>>(p_hln, DIM, p_wip,
                                                             nullptr, nullptr, p_xz,
                                                             NROWS, 2 * D_INNER, DIM);
    }

    // 2. u = silu(conv(xm)) — normal + transposed layouts
    {
        dim3 grid(LSEQ / 32, D_INNER / 32, BATCH);
        conv_silu_T_kernel<<<grid, dim3(32, 8)>>>(conv_w, conv_b);
    }

    // 3. x_dbl = u @ x_proj_w^T [8192,64] K=1024, split-K=4 (256 CTAs)
    cudaMemsetAsync(p_xdbl, 0, (size_t)NROWS * XDBL * sizeof(float));
    {
        dim3 grid(XDBL / 64, NROWS / 128, 4);
        tgemm_kernel<64, EPI_NONE, 4, true><<<grid, 256>>>(p_xconv, D_INNER, p_wxp,
                                                           nullptr, nullptr, p_xdbl,
                                                           NROWS, XDBL, D_INNER);
    }

    // 4. deltaT = softplus(dt @ dt_proj_w^T + b), stored transposed (512 CTAs)
    {
        dim3 grid(D_INNER / 128, NROWS / 128);
        tgemm_kernel<128, EPI_SOFTPL_T, 1, true><<<grid, 256>>>(p_xdbl, XDBL, p_wdt,
                                                                dt_proj_b, nullptr, p_dT,
                                                                NROWS, D_INNER, DT_RANK);
    }

    // 5/6/7. chunked selective scan (pass2 rounds y to tf32)
    {
        dim3 grid(CS, D_INNER / 16, BATCH);
        scan_pass1<<<grid, 256>>>(A_log);
        scan_combine<<<(BATCH * D_INNER * D_STATE) / 256, 256>>>(A_log);
        scan_pass2<<<grid, 256>>>(A_log, Dv);
    }

    // 8. h_out = y @ mix_out_w^T [8192,512] K=1024, split-K=2 (512 CTAs)
    cudaMemsetAsync(p_hout, 0, (size_t)NROWS * DIM * sizeof(float));
    {
        dim3 grid(DIM / 128, NROWS / 128, 2);
        tgemm_kernel<128, EPI_NONE, 2, false><<<grid, 256>>>(p_yscan, D_INNER, p_wmo,
                                                             nullptr, nullptr, p_hout,
                                                             NROWS, DIM, D_INNER);
    }

    // 8b. round h_out to tf32 (feeds only match/geom GEMMs)
    round_buf_kernel<<<(NROWS * DIM / 4 + 255) / 256, 256>>>(p_hout, NROWS * DIM / 4);

    // 9. match_pre = residual + h_out @ match_w^T + match_b (256 CTAs)
    {
        dim3 grid(DIM / 128, NROWS / 128);
        tgemm_kernel<128, EPI_RESID, 1, false><<<grid, 256>>>(p_hout, DIM, p_wma,
                                                              match_b, x, p_match,
                                                              NROWS, DIM, DIM);
    }

    // 10. geom_pre = h_out @ geom_w^T + geom_b [8192,256] K=512, split-K=2 (256 CTAs)
    cudaMemsetAsync(p_geom, 0, (size_t)NROWS * D_GEOM * sizeof(float));
    {
        dim3 grid(D_GEOM / 128, NROWS / 128, 2);
        tgemm_kernel<128, EPI_BIAS, 2, false><<<grid, 256>>>(p_hout, DIM, p_wge,
                                                             geom_b, nullptr, p_geom,
                                                             NROWS, D_GEOM, DIM);
    }

    // 11/12. final layernorms into d_out
    layernorm_kernel<false><<<NROWS, 256>>>(p_match, normm_w, normm_b, out_match, DIM);
    layernorm_kernel<false><<<NROWS, 256>>>(p_geom,  normg_w, normg_b, out_geom,  D_GEOM);
}